// round 12
// baseline (speedup 1.0000x reference)
#include <cuda_runtime.h>
#include <cuda_bf16.h>
#include <cstdint>

#define DIM 64

// Compact B blocks, bf16 hi/lo, built directly by build_weights:
//   [tap t=slab*5+c][blk 0..3][half hi/lo][16 rows x 48B (16 n*2B + pad)]
//   blk0=k00, blk1=base01, blk2=b10(raw), blk3=v11(diag)
__device__ __align__(16) unsigned char g_Bc[125 * 4 * 2 * 768];
// channel-last bf16 split of x: [b][x][y][z][ci']  (PERMUTED channels)
__device__ __align__(128) __nv_bfloat16 g_xhi[2ull * 64 * 64 * 64 * 64];
__device__ __align__(128) __nv_bfloat16 g_xlo[2ull * 64 * 64 * 64 * 64];
// 16B zero source for halo cp.async
__device__ __align__(16) float g_zero[4] = {0.f, 0.f, 0.f, 0.f};

// channel permutation: orig 16+3u+i  ->  16+16i+u ; identity below 16
__device__ __forceinline__ int perm_ch(int ci) {
    if (ci < 16) return ci;
    const int r = ci - 16;
    return 16 + (r % 3) * 16 + (r / 3);
}

// ---------------------------------------------------------------------------
// Kernel 1: build compact B blocks (bf16 hi/lo) straight from inputs
// ---------------------------------------------------------------------------
__global__ void build_weights(const float* __restrict__ lw0,
                              const float* __restrict__ lw1,
                              const float* __restrict__ tp)
{
    const int t  = blockIdx.x;            // 0..124, t = (a*5+bb)*5 + c
    const int a  = t / 25;
    const int b2 = (t / 5) % 5;
    const int c  = t % 5;

    const float lx = -1.f + 0.5f * (float)a;
    const float ly = -1.f + 0.5f * (float)b2;
    const float lz = -1.f + 0.5f * (float)c;
    const float d  = sqrtf(lx*lx + ly*ly + lz*lz);

    const float scale = cosf(3.14159265358979323846f * d) / 11.180339887498949f;
    float coef[5];
#pragma unroll
    for (int s = 0; s < 5; s++) {
        float u = (d - 0.25f * (float)s) / 0.25f;
        coef[s] = expf(-u * u) * (1.0f / 1.12f) * scale;
    }

    const int u_ = threadIdx.x >> 4;
    const int w_ = threadIdx.x & 15;
    const int m  = u_ * 16 + w_;

    float eA = 0.f, eB = 0.f, eC = 0.f, eD = 0.f;
#pragma unroll
    for (int s = 0; s < 5; s++) {
        const float cs = coef[s];
        eA += cs * tp[s * 1024 +   0 + m];
        eB += cs * tp[s * 1024 + 256 + m];
        eC += cs * tp[s * 1024 + 512 + m];
        eD += cs * tp[s * 1024 + 768 + m];
    }

    const float A0  = 0.17677669529663689f;   // sqrt(1/32)
    const float A1  = 0.30618621784789724f;   // sqrt(3/32)
    const float IS3 = 0.57735026918962576f;   // 1/sqrt(3)
    const float inv = 0.25f;
    const bool  center = (t == 62);           // (2,2,2)

    float blkv[4];
    blkv[0] = 0.1f * A0 * eA + (center ? inv * lw0[m] : 0.f);   // k00
    blkv[1] = 0.1f * A1 * IS3 * eB;                              // base01
    blkv[2] = 0.1f * A0 * IS3 * eD;                              // b10 (raw)
    blkv[3] = 0.1f * A1 * IS3 * eC + (center ? inv * lw1[m] : 0.f); // v11

#pragma unroll
    for (int blk = 0; blk < 4; blk++) {
        const float v = blkv[blk];
        const __nv_bfloat16 h = __float2bfloat16(v);
        const __nv_bfloat16 l = __float2bfloat16(v - __bfloat162float(h));
        const size_t off = ((size_t)(t * 4 + blk) * 2) * 768
                         + (size_t)u_ * 48 + (size_t)w_ * 2;
        *(__nv_bfloat16*)(g_Bc + off)       = h;
        *(__nv_bfloat16*)(g_Bc + off + 768) = l;
    }
}

// ---------------------------------------------------------------------------
// Kernel 2: split + transpose x -> channel-last (PERMUTED) bf16 hi/lo
// ---------------------------------------------------------------------------
__global__ void __launch_bounds__(256) xsplit(const float* __restrict__ x)
{
    __shared__ float s[64][65];
    const int gid = blockIdx.x;            // b*4096 + xx*64 + y
    const int y  = gid & 63;
    const int xx = (gid >> 6) & 63;
    const int b  = gid >> 12;
    const int tid = threadIdx.x;
    const int zz = tid & 63;
    const int cq = tid >> 6;               // 0..3

    const size_t sp = (size_t)(xx * 64 + y) * 64;
#pragma unroll
    for (int r = 0; r < 16; r++) {
        const int ci = cq * 16 + r;
        s[ci][zz] = x[(size_t)(b * 64 + ci) * 262144 + sp + zz];
    }
    __syncthreads();

    __nv_bfloat16* oH = g_xhi + (((size_t)(b * 64 + xx) * 64 + y) << 12);
    __nv_bfloat16* oL = g_xlo + (((size_t)(b * 64 + xx) * 64 + y) << 12);
    const int ci_w = tid & 63;
    const int cp   = perm_ch(ci_w);
#pragma unroll
    for (int r = 0; r < 16; r++) {
        const int z = cq * 16 + r;
        const float v = s[ci_w][z];
        __nv_bfloat16 h = __float2bfloat16(v);
        __nv_bfloat16 l = __float2bfloat16(v - __bfloat162float(h));
        oH[z * 64 + cp] = h;
        oL[z * 64 + cp] = l;
    }
}

// ---------------------------------------------------------------------------
// PTX helpers (all base-target sm_80+ instructions)
// ---------------------------------------------------------------------------
__device__ __forceinline__ uint32_t smem_u32(const void* p) {
    uint32_t a;
    asm("{ .reg .u64 t; cvta.to.shared.u64 t, %1; cvt.u32.u64 %0, t; }"
        : "=r"(a) : "l"(p));
    return a;
}
__device__ __forceinline__ void ldsm4(uint32_t& r0, uint32_t& r1,
                                      uint32_t& r2, uint32_t& r3, uint32_t a) {
    asm volatile("ldmatrix.sync.aligned.m8n8.x4.shared.b16 {%0,%1,%2,%3}, [%4];"
                 : "=r"(r0), "=r"(r1), "=r"(r2), "=r"(r3) : "r"(a));
}
__device__ __forceinline__ void ldsm4t(uint32_t& r0, uint32_t& r1,
                                       uint32_t& r2, uint32_t& r3, uint32_t a) {
    asm volatile("ldmatrix.sync.aligned.m8n8.x4.trans.shared.b16 {%0,%1,%2,%3}, [%4];"
                 : "=r"(r0), "=r"(r1), "=r"(r2), "=r"(r3) : "r"(a));
}
__device__ __forceinline__ void mma16816(float* d, uint32_t a0, uint32_t a1,
                                         uint32_t a2, uint32_t a3,
                                         uint32_t b0, uint32_t b1) {
    asm volatile(
        "mma.sync.aligned.m16n8k16.row.col.f32.bf16.bf16.f32 "
        "{%0,%1,%2,%3}, {%4,%5,%6,%7}, {%8,%9}, {%0,%1,%2,%3};"
        : "+f"(d[0]), "+f"(d[1]), "+f"(d[2]), "+f"(d[3])
        : "r"(a0), "r"(a1), "r"(a2), "r"(a3), "r"(b0), "r"(b1));
}
__device__ __forceinline__ void cpa16(uint32_t dst, const void* src) {
    asm volatile("cp.async.cg.shared.global [%0], [%1], 16;"
                 :: "r"(dst), "l"(src));
}
#define CP_COMMIT() asm volatile("cp.async.commit_group;" ::: "memory")
#define CP_WAIT0()  asm volatile("cp.async.wait_group 0;" ::: "memory")

// ---------------------------------------------------------------------------
// SMEM map (bytes, within dynamic smem)
//   B: 2 bufs x 30720 (5c x 4blk x 2half x 768B)    = 61440
//   Input: 2 stages x 4 (ys,half) x 64 rows x 128B  = 65536
// ---------------------------------------------------------------------------
#define SM_B     0
#define SM_IN    61440
#define SM_ZERO  126976
#define SM_TOT   127104
#define PLANE_B  30720

// ---------------------------------------------------------------------------
// Kernel 3: mma.sync implicit-GEMM conv, fully factored block structure
//   per c-tap (36 MMAs): blk0 k00; blk1 k01->P(rank-1 out); blk2 Ac*b10
//   (rank-1 in, A combined in fp32); blk3 v11 diag x3.
// ---------------------------------------------------------------------------
__global__ void __launch_bounds__(256, 1)
conv_mma(float* __restrict__ out)
{
    extern __shared__ char smem[];
    const uint32_t sb = smem_u32(smem);
    const int tid  = threadIdx.x;
    const int wid  = tid >> 5;
    const int lane = tid & 31;

    const int gid = blockIdx.x;
    const int y0  = (gid & 31) * 2;
    const int x0  = (gid >> 5) & 63;
    const int b   = gid >> 11;

    if (tid < 8)
        *(float4*)(smem + SM_ZERO + tid * 16) = make_float4(0.f, 0.f, 0.f, 0.f);

    // plane list (uniform across block)
    int pslab[25], pxi[25], pbb[25];
    int npl = 0;
#pragma unroll
    for (int a = 0; a < 5; a++) {
        const int xi = x0 + a - 2;
        if ((unsigned)xi >= 64u) continue;
#pragma unroll
        for (int bb = 0; bb < 5; bb++) {
            const int yi0 = y0 + bb - 2;
            const int yi1 = yi0 + 1;
            if ((unsigned)yi0 >= 64u && (unsigned)yi1 >= 64u) continue;
            pslab[npl] = a * 5 + bb;
            pxi[npl]   = xi;
            pbb[npl]   = bb;
            npl++;
        }
    }

    // per-warp / per-thread constants
    const int zb   = (wid & 3) * 16;
    const int ysw  = wid >> 2;
    const int mloc = (lane & 7) + ((lane >> 3) & 1) * 8;
    const int ksub = lane >> 4;
    const uint32_t zeroAddr = sb + SM_ZERO;
    const uint32_t bl_off = (uint32_t)(lane & 15) * 48u + (uint32_t)(lane >> 4) * 16u;
    float acc[8][4];
#pragma unroll
    for (int nt = 0; nt < 8; nt++)
#pragma unroll
        for (int i = 0; i < 4; i++) acc[nt][i] = 0.f;

    // staging lambdas -------------------------------------------------------
    auto stage_B = [&](int p, int buf) {
        const unsigned char* src = g_Bc + (size_t)pslab[p] * PLANE_B;
        const uint32_t dst0 = sb + SM_B + buf * PLANE_B;
#pragma unroll
        for (int i = 0; i < 8; i++) {
            const int id = tid + i * 256;            // 0..2047
            if (id < PLANE_B / 16)
                cpa16(dst0 + id * 16, src + id * 16);
        }
    };
    auto stage_In = [&](int p, int stg) {
        const int xi = pxi[p], bb = pbb[p];
#pragma unroll
        for (int i = 0; i < 8; i++) {
            const int id   = tid + i * 256;          // 0..2047
            const int col  = id & 7;
            const int z    = (id >> 3) & 63;
            const int half = (id >> 9) & 1;
            const int ys   = id >> 10;
            const int yi   = y0 + ys + bb - 2;
            const bool ok  = (unsigned)yi < 64u;
            const __nv_bfloat16* g = half ? g_xlo : g_xhi;
            const void* src = ok
                ? (const void*)(g + (((size_t)(b * 64 + xi) * 64 + yi) << 12)
                                + z * 64 + col * 8)
                : (const void*)g_zero;
            const uint32_t dst = sb + SM_IN + stg * 32768
                               + (ys * 2 + half) * 8192 + z * 128
                               + (((uint32_t)col * 16u) ^ (((uint32_t)z & 7u) << 4));
            cpa16(dst, src);
        }
    };

    // prologue
    stage_B(0, 0);
    stage_In(0, 0);
    CP_COMMIT();
    CP_WAIT0();
    __syncthreads();

#pragma unroll 1
    for (int p = 0; p < npl; p++) {
        if (p + 1 < npl) {
            stage_B(p + 1, (p + 1) & 1);
            stage_In(p + 1, (p + 1) & 1);
            CP_COMMIT();
        }

        const uint32_t Bb  = sb + SM_B + (p & 1) * PLANE_B;
        const uint32_t inH = sb + SM_IN + (p & 1) * 32768 + ysw * 16384;
        const uint32_t inL = inH + 8192;

        const int slab = pslab[p];
        const int pa   = slab / 5;
        const int pb   = slab - pa * 5;
        const float lx = -1.f + 0.5f * (float)pa;
        const float ly = -1.f + 0.5f * (float)pb;

        // ---- compute: 5 c-taps, fully factored blocks ----
#pragma unroll 1
        for (int c = 0; c < 5; c++) {
            const float lz = -1.f + 0.5f * (float)c;
            const float d2 = lx*lx + ly*ly + lz*lz;
            float s[3];
            if (d2 > 0.f) {
                const float ri = rsqrtf(d2) * 1.7320508075688772f;
                s[0] = ly * ri; s[1] = lz * ri; s[2] = lx * ri;
            } else { s[0] = s[1] = s[2] = 0.f; }

            // A fragments (all 4 q-blocks, hi+lo)
            const int zi = zb + mloc + c - 2;
            const bool vz = (unsigned)zi < 64u;
            const uint32_t jx   = ((uint32_t)zi & 7u) << 4;
            const uint32_t arow = (uint32_t)zi * 128u;
            uint32_t ah[4][4], al[4][4];
#pragma unroll
            for (int q = 0; q < 4; q++) {
                const uint32_t acol = ((uint32_t)(q * 32 + ksub * 16)) ^ jx;
                const uint32_t aH = vz ? (inH + arow + acol) : zeroAddr;
                const uint32_t aL = vz ? (inL + arow + acol) : zeroAddr;
                ldsm4(ah[q][0], ah[q][1], ah[q][2], ah[q][3], aH);
                ldsm4(al[q][0], al[q][1], al[q][2], al[q][3], aL);
            }

            // Combined A for k10: Ac = sum_i s[i] * x_{q=i+1} (fp32, re-split)
            uint32_t ach[4], acl[4];
#pragma unroll
            for (int r = 0; r < 4; r++) {
                const float2 f1h = __bfloat1622float2(*(const __nv_bfloat162*)&ah[1][r]);
                const float2 f1l = __bfloat1622float2(*(const __nv_bfloat162*)&al[1][r]);
                const float2 f2h = __bfloat1622float2(*(const __nv_bfloat162*)&ah[2][r]);
                const float2 f2l = __bfloat1622float2(*(const __nv_bfloat162*)&al[2][r]);
                const float2 f3h = __bfloat1622float2(*(const __nv_bfloat162*)&ah[3][r]);
                const float2 f3l = __bfloat1622float2(*(const __nv_bfloat162*)&al[3][r]);
                const float vx = s[0]*(f1h.x+f1l.x) + s[1]*(f2h.x+f2l.x) + s[2]*(f3h.x+f3l.x);
                const float vy = s[0]*(f1h.y+f1l.y) + s[1]*(f2h.y+f2l.y) + s[2]*(f3h.y+f3l.y);
                const __nv_bfloat162 hh = __floats2bfloat162_rn(vx, vy);
                const float2 fh = __bfloat1622float2(hh);
                const __nv_bfloat162 ll = __floats2bfloat162_rn(vx - fh.x, vy - fh.y);
                ach[r] = *(const uint32_t*)&hh;
                acl[r] = *(const uint32_t*)&ll;
            }

            const uint32_t cbase = Bb + (uint32_t)(c * 4 * 2) * 768u + bl_off;
            uint32_t bh0, bh1, bh2, bh3, bl0, bl1, bl2, bl3;

            // ---- blk0: k00 (A q=0 -> acc n-block 0) ----
            ldsm4t(bh0, bh1, bh2, bh3, cbase + 0 * 1536);
            ldsm4t(bl0, bl1, bl2, bl3, cbase + 0 * 1536 + 768);
            mma16816(acc[0], ah[0][0], ah[0][1], ah[0][2], ah[0][3], bh0, bh1);
            mma16816(acc[1], ah[0][0], ah[0][1], ah[0][2], ah[0][3], bh2, bh3);
            mma16816(acc[0], al[0][0], al[0][1], al[0][2], al[0][3], bh0, bh1);
            mma16816(acc[1], al[0][0], al[0][1], al[0][2], al[0][3], bh2, bh3);
            mma16816(acc[0], ah[0][0], ah[0][1], ah[0][2], ah[0][3], bl0, bl1);
            mma16816(acc[1], ah[0][0], ah[0][1], ah[0][2], ah[0][3], bl2, bl3);

            // ---- blk1: k01 rank-1 -> P, then scaled into acc blocks 1..3 ----
            {
                float P[2][4];
#pragma unroll
                for (int j = 0; j < 2; j++)
#pragma unroll
                    for (int r = 0; r < 4; r++) P[j][r] = 0.f;
                ldsm4t(bh0, bh1, bh2, bh3, cbase + 1 * 1536);
                ldsm4t(bl0, bl1, bl2, bl3, cbase + 1 * 1536 + 768);
                mma16816(P[0], ah[0][0], ah[0][1], ah[0][2], ah[0][3], bh0, bh1);
                mma16816(P[1], ah[0][0], ah[0][1], ah[0][2], ah[0][3], bh2, bh3);
                mma16816(P[0], al[0][0], al[0][1], al[0][2], al[0][3], bh0, bh1);
                mma16816(P[1], al[0][0], al[0][1], al[0][2], al[0][3], bh2, bh3);
                mma16816(P[0], ah[0][0], ah[0][1], ah[0][2], ah[0][3], bl0, bl1);
                mma16816(P[1], ah[0][0], ah[0][1], ah[0][2], ah[0][3], bl2, bl3);
#pragma unroll
                for (int k = 0; k < 3; k++) {
                    const float sk = s[k];
#pragma unroll
                    for (int j = 0; j < 2; j++)
#pragma unroll
                        for (int r = 0; r < 4; r++)
                            acc[2 * (k + 1) + j][r] += sk * P[j][r];
                }
            }

            // ---- blk2: combined-A x raw b10 -> acc n-block 0 ----
            ldsm4t(bh0, bh1, bh2, bh3, cbase + 2 * 1536);
            ldsm4t(bl0, bl1, bl2, bl3, cbase + 2 * 1536 + 768);
            mma16816(acc[0], ach[0], ach[1], ach[2], ach[3], bh0, bh1);
            mma16816(acc[1], ach[0], ach[1], ach[2], ach[3], bh2, bh3);
            mma16816(acc[0], acl[0], acl[1], acl[2], acl[3], bh0, bh1);
            mma16816(acc[1], acl[0], acl[1], acl[2], acl[3], bh2, bh3);
            mma16816(acc[0], ach[0], ach[1], ach[2], ach[3], bl0, bl1);
            mma16816(acc[1], ach[0], ach[1], ach[2], ach[3], bl2, bl3);

            // ---- blk3: k11 diagonal, same B for all 3 i ----
            {
                ldsm4t(bh0, bh1, bh2, bh3, cbase + 3 * 1536);
                ldsm4t(bl0, bl1, bl2, bl3, cbase + 3 * 1536 + 768);
#pragma unroll
                for (int k = 0; k < 3; k++) {
                    const int q = k + 1;
                    float* d0 = acc[2 * (k + 1)];
                    float* d1 = acc[2 * (k + 1) + 1];
                    mma16816(d0, ah[q][0], ah[q][1], ah[q][2], ah[q][3], bh0, bh1);
                    mma16816(d1, ah[q][0], ah[q][1], ah[q][2], ah[q][3], bh2, bh3);
                    mma16816(d0, al[q][0], al[q][1], al[q][2], al[q][3], bh0, bh1);
                    mma16816(d1, al[q][0], al[q][1], al[q][2], al[q][3], bh2, bh3);
                    mma16816(d0, ah[q][0], ah[q][1], ah[q][2], ah[q][3], bl0, bl1);
                    mma16816(d1, ah[q][0], ah[q][1], ah[q][2], ah[q][3], bl2, bl3);
                }
            }
        }

        if (p + 1 < npl) CP_WAIT0();
        __syncthreads();
    }

    // ---- epilogue: direct global stores, un-permute cout ----
    const int g  = lane >> 2;
    const int cc = lane & 3;
    const int z  = zb + g;
    const int y  = y0 + ysw;
    float* ob = out + ((((size_t)b * 64) * 64 + x0) * 64 + y) * 64 + z;
#pragma unroll
    for (int nt = 0; nt < 8; nt++) {
        const int n0 = nt * 8 + 2 * cc;
        const int ch0 = (n0 < 16) ? n0 : (16 + 3 * ((n0 - 16) & 15) + ((n0 - 16) >> 4));
        const int n1 = n0 + 1;
        const int ch1 = (n1 < 16) ? n1 : (16 + 3 * ((n1 - 16) & 15) + ((n1 - 16) >> 4));
        float* p0 = ob + (size_t)ch0 * 262144;
        float* p1 = ob + (size_t)ch1 * 262144;
        p0[0] = acc[nt][0];
        p1[0] = acc[nt][1];
        p0[8] = acc[nt][2];
        p1[8] = acc[nt][3];
    }
}

// ---------------------------------------------------------------------------
// Launch
// ---------------------------------------------------------------------------
extern "C" void kernel_launch(void* const* d_in, const int* in_sizes, int n_in,
                              void* d_out, int out_size)
{
    const float* x   = (const float*)d_in[0];
    const float* lw0 = (const float*)d_in[1];
    const float* lw1 = (const float*)d_in[2];
    const float* tp  = (const float*)d_in[3];
    float* out = (float*)d_out;

    xsplit<<<2 * 64 * 64, 256>>>(x);
    build_weights<<<125, 256>>>(lw0, lw1, tp);

    cudaFuncSetAttribute(conv_mma, cudaFuncAttributeMaxDynamicSharedMemorySize,
                         SM_TOT);
    conv_mma<<<2 * 64 * 32, 256, SM_TOT>>>(out);
}

// round 13
// speedup vs baseline: 1.0684x; 1.0684x over previous
#include <cuda_runtime.h>
#include <cuda_bf16.h>
#include <cstdint>

#define DIM 64

// Compact B blocks, bf16 hi/lo, built directly by build_weights:
//   [tap t=slab*5+c][blk 0..5][half hi/lo][16 rows x 48B (16 n*2B + pad)]
//   blk0=k00, blk1=base01, blk2..4=b10*sh[i], blk5=v11(diag)
__device__ __align__(16) unsigned char g_Bc[125 * 6 * 2 * 768];
// channel-last bf16 split of x: [b][x][y][z][ci']  (PERMUTED channels)
__device__ __align__(128) __nv_bfloat16 g_xhi[2ull * 64 * 64 * 64 * 64];
__device__ __align__(128) __nv_bfloat16 g_xlo[2ull * 64 * 64 * 64 * 64];
// 16B zero source for halo cp.async
__device__ __align__(16) float g_zero[4] = {0.f, 0.f, 0.f, 0.f};

// channel permutation: orig 16+3u+i  ->  16+16i+u ; identity below 16
__device__ __forceinline__ int perm_ch(int ci) {
    if (ci < 16) return ci;
    const int r = ci - 16;
    return 16 + (r % 3) * 16 + (r / 3);
}

// ---------------------------------------------------------------------------
// Kernel 1: build compact B blocks (bf16 hi/lo) straight from inputs (R11)
// ---------------------------------------------------------------------------
__global__ void build_weights(const float* __restrict__ lw0,
                              const float* __restrict__ lw1,
                              const float* __restrict__ tp)
{
    const int t  = blockIdx.x;            // 0..124, t = (a*5+bb)*5 + c
    const int a  = t / 25;
    const int b2 = (t / 5) % 5;
    const int c  = t % 5;

    const float lx = -1.f + 0.5f * (float)a;
    const float ly = -1.f + 0.5f * (float)b2;
    const float lz = -1.f + 0.5f * (float)c;
    const float d  = sqrtf(lx*lx + ly*ly + lz*lz);

    float ux = 0.f, uy = 0.f, uz = 0.f;
    if (d > 0.f) { ux = lx / d; uy = ly / d; uz = lz / d; }
    const float SQ3 = 1.7320508075688772f;
    const float s0 = SQ3 * uy, s1 = SQ3 * uz, s2 = SQ3 * ux;

    const float scale = cosf(3.14159265358979323846f * d) / 11.180339887498949f;
    float coef[5];
#pragma unroll
    for (int s = 0; s < 5; s++) {
        float u = (d - 0.25f * (float)s) / 0.25f;
        coef[s] = expf(-u * u) * (1.0f / 1.12f) * scale;
    }

    const int u_ = threadIdx.x >> 4;
    const int w_ = threadIdx.x & 15;
    const int m  = u_ * 16 + w_;

    float eA = 0.f, eB = 0.f, eC = 0.f, eD = 0.f;
#pragma unroll
    for (int s = 0; s < 5; s++) {
        const float cs = coef[s];
        eA += cs * tp[s * 1024 +   0 + m];
        eB += cs * tp[s * 1024 + 256 + m];
        eC += cs * tp[s * 1024 + 512 + m];
        eD += cs * tp[s * 1024 + 768 + m];
    }

    const float A0  = 0.17677669529663689f;   // sqrt(1/32)
    const float A1  = 0.30618621784789724f;   // sqrt(3/32)
    const float IS3 = 0.57735026918962576f;   // 1/sqrt(3)
    const float inv = 0.25f;
    const bool  center = (t == 62);           // (2,2,2)
    const float b10 = 0.1f * A0 * IS3 * eD;

    float blkv[6];
    blkv[0] = 0.1f * A0 * eA + (center ? inv * lw0[m] : 0.f);
    blkv[1] = 0.1f * A1 * IS3 * eB;
    blkv[2] = b10 * s0;
    blkv[3] = b10 * s1;
    blkv[4] = b10 * s2;
    blkv[5] = 0.1f * A1 * IS3 * eC + (center ? inv * lw1[m] : 0.f);

#pragma unroll
    for (int blk = 0; blk < 6; blk++) {
        const float v = blkv[blk];
        const __nv_bfloat16 h = __float2bfloat16(v);
        const __nv_bfloat16 l = __float2bfloat16(v - __bfloat162float(h));
        const size_t off = ((size_t)(t * 6 + blk) * 2) * 768
                         + (size_t)u_ * 48 + (size_t)w_ * 2;
        *(__nv_bfloat16*)(g_Bc + off)       = h;
        *(__nv_bfloat16*)(g_Bc + off + 768) = l;
    }
}

// ---------------------------------------------------------------------------
// Kernel 2: split + transpose x -> channel-last (PERMUTED) bf16 hi/lo
// ---------------------------------------------------------------------------
__global__ void __launch_bounds__(256) xsplit(const float* __restrict__ x)
{
    __shared__ float s[64][65];
    const int gid = blockIdx.x;            // b*4096 + xx*64 + y
    const int y  = gid & 63;
    const int xx = (gid >> 6) & 63;
    const int b  = gid >> 12;
    const int tid = threadIdx.x;
    const int zz = tid & 63;
    const int cq = tid >> 6;               // 0..3

    const size_t sp = (size_t)(xx * 64 + y) * 64;
#pragma unroll
    for (int r = 0; r < 16; r++) {
        const int ci = cq * 16 + r;
        s[ci][zz] = x[(size_t)(b * 64 + ci) * 262144 + sp + zz];
    }
    __syncthreads();

    __nv_bfloat16* oH = g_xhi + (((size_t)(b * 64 + xx) * 64 + y) << 12);
    __nv_bfloat16* oL = g_xlo + (((size_t)(b * 64 + xx) * 64 + y) << 12);
    const int ci_w = tid & 63;
    const int cp   = perm_ch(ci_w);
#pragma unroll
    for (int r = 0; r < 16; r++) {
        const int z = cq * 16 + r;
        const float v = s[ci_w][z];
        __nv_bfloat16 h = __float2bfloat16(v);
        __nv_bfloat16 l = __float2bfloat16(v - __bfloat162float(h));
        oH[z * 64 + cp] = h;
        oL[z * 64 + cp] = l;
    }
}

// ---------------------------------------------------------------------------
// PTX helpers (all base-target sm_80+ instructions)
// ---------------------------------------------------------------------------
__device__ __forceinline__ uint32_t smem_u32(const void* p) {
    uint32_t a;
    asm("{ .reg .u64 t; cvta.to.shared.u64 t, %1; cvt.u32.u64 %0, t; }"
        : "=r"(a) : "l"(p));
    return a;
}
__device__ __forceinline__ void ldsm4(uint32_t& r0, uint32_t& r1,
                                      uint32_t& r2, uint32_t& r3, uint32_t a) {
    asm volatile("ldmatrix.sync.aligned.m8n8.x4.shared.b16 {%0,%1,%2,%3}, [%4];"
                 : "=r"(r0), "=r"(r1), "=r"(r2), "=r"(r3) : "r"(a));
}
__device__ __forceinline__ void ldsm4t(uint32_t& r0, uint32_t& r1,
                                       uint32_t& r2, uint32_t& r3, uint32_t a) {
    asm volatile("ldmatrix.sync.aligned.m8n8.x4.trans.shared.b16 {%0,%1,%2,%3}, [%4];"
                 : "=r"(r0), "=r"(r1), "=r"(r2), "=r"(r3) : "r"(a));
}
__device__ __forceinline__ void mma16816(float* d, uint32_t a0, uint32_t a1,
                                         uint32_t a2, uint32_t a3,
                                         uint32_t b0, uint32_t b1) {
    asm volatile(
        "mma.sync.aligned.m16n8k16.row.col.f32.bf16.bf16.f32 "
        "{%0,%1,%2,%3}, {%4,%5,%6,%7}, {%8,%9}, {%0,%1,%2,%3};"
        : "+f"(d[0]), "+f"(d[1]), "+f"(d[2]), "+f"(d[3])
        : "r"(a0), "r"(a1), "r"(a2), "r"(a3), "r"(b0), "r"(b1));
}
__device__ __forceinline__ void cpa16(uint32_t dst, const void* src) {
    asm volatile("cp.async.cg.shared.global [%0], [%1], 16;"
                 :: "r"(dst), "l"(src));
}
#define CP_COMMIT() asm volatile("cp.async.commit_group;" ::: "memory")
#define CP_WAIT0()  asm volatile("cp.async.wait_group 0;" ::: "memory")

// ---------------------------------------------------------------------------
// SMEM map (bytes, within dynamic smem)
//   B: 2 bufs x 46080 (5c x 6blk x 2half x 768B)        =  92160
//   Input: 2 stages x 4 ys x 2 half x 64 rows x 128B    = 131072
// ---------------------------------------------------------------------------
#define SM_B     0
#define SM_IN    92160
#define SM_ZERO  223232
#define SM_TOT   223360
#define PLANE_B  46080

// ---------------------------------------------------------------------------
// Kernel 3: mma.sync implicit-GEMM conv, R11 block structure, M=256 per CTA
//   CTA = (b, x0, y-quad). 8 warps; warp: zb=(wid&3)*16, ys pair = (wid>>2)*2
//   Each warp: 2 m16 tiles (adjacent y), B fragments shared across both.
// ---------------------------------------------------------------------------
__global__ void __launch_bounds__(256, 1)
conv_mma(float* __restrict__ out)
{
    extern __shared__ char smem[];
    const uint32_t sb = smem_u32(smem);
    const int tid  = threadIdx.x;
    const int wid  = tid >> 5;
    const int lane = tid & 31;

    const int gid = blockIdx.x;                  // 2*64*16 = 2048 CTAs
    const int y0  = (gid & 15) * 4;
    const int x0  = (gid >> 4) & 63;
    const int b   = gid >> 10;

    if (tid < 8)
        *(float4*)(smem + SM_ZERO + tid * 16) = make_float4(0.f, 0.f, 0.f, 0.f);

    // plane list (uniform across block)
    int pslab[25], pxi[25], pbb[25];
    int npl = 0;
#pragma unroll
    for (int a = 0; a < 5; a++) {
        const int xi = x0 + a - 2;
        if ((unsigned)xi >= 64u) continue;
#pragma unroll
        for (int bb = 0; bb < 5; bb++) {
            const int ylo = y0 + bb - 2;         // ys=0 row
            const int yhi = ylo + 3;             // ys=3 row
            if (yhi < 0 || ylo > 63) continue;
            pslab[npl] = a * 5 + bb;
            pxi[npl]   = xi;
            pbb[npl]   = bb;
            npl++;
        }
    }

    // per-warp / per-thread constants
    const int zb   = (wid & 3) * 16;
    const int ysw  = wid >> 2;                   // 0/1 -> ys pair base = ysw*2
    const int mloc = (lane & 7) + ((lane >> 3) & 1) * 8;
    const int ksub = lane >> 4;
    const uint32_t zeroAddr = sb + SM_ZERO;
    const uint32_t bl_off = (uint32_t)(lane & 15) * 48u + (uint32_t)(lane >> 4) * 16u;
    float acc[2][8][4];
#pragma unroll
    for (int mt = 0; mt < 2; mt++)
#pragma unroll
        for (int nt = 0; nt < 8; nt++)
#pragma unroll
            for (int i = 0; i < 4; i++) acc[mt][nt][i] = 0.f;

    // staging lambdas -------------------------------------------------------
    auto stage_B = [&](int p, int buf) {
        const unsigned char* src = g_Bc + (size_t)pslab[p] * PLANE_B;
        const uint32_t dst0 = sb + SM_B + buf * PLANE_B;
#pragma unroll
        for (int i = 0; i < 12; i++) {
            const int id = tid + i * 256;        // 0..2879
            if (id < PLANE_B / 16)
                cpa16(dst0 + id * 16, src + id * 16);
        }
    };
    auto stage_In = [&](int p, int stg) {
        const int xi = pxi[p], bb = pbb[p];
#pragma unroll
        for (int i = 0; i < 16; i++) {
            const int id   = tid + i * 256;      // 0..4095
            const int col  = id & 7;
            const int z    = (id >> 3) & 63;
            const int half = (id >> 9) & 1;
            const int ys   = (id >> 10) & 3;
            const int yi   = y0 + ys + bb - 2;
            const bool ok  = (unsigned)yi < 64u;
            const __nv_bfloat16* g = half ? g_xlo : g_xhi;
            const void* src = ok
                ? (const void*)(g + (((size_t)(b * 64 + xi) * 64 + yi) << 12)
                                + z * 64 + col * 8)
                : (const void*)g_zero;
            const uint32_t dst = sb + SM_IN + stg * 65536
                               + ys * 16384 + half * 8192 + z * 128
                               + (((uint32_t)col * 16u) ^ (((uint32_t)z & 7u) << 4));
            cpa16(dst, src);
        }
    };

    // prologue
    stage_B(0, 0);
    stage_In(0, 0);
    CP_COMMIT();
    CP_WAIT0();
    __syncthreads();

#pragma unroll 1
    for (int p = 0; p < npl; p++) {
        if (p + 1 < npl) {
            stage_B(p + 1, (p + 1) & 1);
            stage_In(p + 1, (p + 1) & 1);
            CP_COMMIT();
        }

        const uint32_t Bb   = sb + SM_B + (p & 1) * PLANE_B;
        const uint32_t inSt = sb + SM_IN + (p & 1) * 65536;

        const int slab = pslab[p];
        const int pa   = slab / 5;
        const int pb   = slab - pa * 5;
        const float lx = -1.f + 0.5f * (float)pa;
        const float ly = -1.f + 0.5f * (float)pb;

        // ---- compute: 5 c-taps, structured blocks, 2 m-tiles per warp ----
#pragma unroll 1
        for (int c = 0; c < 5; c++) {
            const float lz = -1.f + 0.5f * (float)c;
            const float d2 = lx*lx + ly*ly + lz*lz;
            float s[3];
            if (d2 > 0.f) {
                const float ri = rsqrtf(d2) * 1.7320508075688772f;
                s[0] = ly * ri; s[1] = lz * ri; s[2] = lx * ri;
            } else { s[0] = s[1] = s[2] = 0.f; }

            // A fragments: 2 m-tiles x 4 q-blocks, hi+lo
            const int zi = zb + mloc + c - 2;
            const bool vz = (unsigned)zi < 64u;
            const uint32_t jx   = ((uint32_t)zi & 7u) << 4;
            const uint32_t arow = (uint32_t)zi * 128u;
            uint32_t ah[2][4][4], al[2][4][4];
#pragma unroll
            for (int mt = 0; mt < 2; mt++) {
                const uint32_t inH = inSt + (ysw * 2 + mt) * 16384;
                const uint32_t inL = inH + 8192;
#pragma unroll
                for (int q = 0; q < 4; q++) {
                    const uint32_t acol = ((uint32_t)(q * 32 + ksub * 16)) ^ jx;
                    const uint32_t aH = vz ? (inH + arow + acol) : zeroAddr;
                    const uint32_t aL = vz ? (inL + arow + acol) : zeroAddr;
                    ldsm4(ah[mt][q][0], ah[mt][q][1], ah[mt][q][2], ah[mt][q][3], aH);
                    ldsm4(al[mt][q][0], al[mt][q][1], al[mt][q][2], al[mt][q][3], aL);
                }
            }

            const uint32_t cbase = Bb + (uint32_t)(c * 6 * 2) * 768u + bl_off;
            uint32_t bh0, bh1, bh2, bh3, bl0, bl1, bl2, bl3;

            // ---- blk0: k00 (A q=0 -> acc n-block 0) ----
            ldsm4t(bh0, bh1, bh2, bh3, cbase + 0 * 1536);
            ldsm4t(bl0, bl1, bl2, bl3, cbase + 0 * 1536 + 768);
#pragma unroll
            for (int mt = 0; mt < 2; mt++) {
                mma16816(acc[mt][0], ah[mt][0][0], ah[mt][0][1], ah[mt][0][2], ah[mt][0][3], bh0, bh1);
                mma16816(acc[mt][1], ah[mt][0][0], ah[mt][0][1], ah[mt][0][2], ah[mt][0][3], bh2, bh3);
                mma16816(acc[mt][0], al[mt][0][0], al[mt][0][1], al[mt][0][2], al[mt][0][3], bh0, bh1);
                mma16816(acc[mt][1], al[mt][0][0], al[mt][0][1], al[mt][0][2], al[mt][0][3], bh2, bh3);
                mma16816(acc[mt][0], ah[mt][0][0], ah[mt][0][1], ah[mt][0][2], ah[mt][0][3], bl0, bl1);
                mma16816(acc[mt][1], ah[mt][0][0], ah[mt][0][1], ah[mt][0][2], ah[mt][0][3], bl2, bl3);
            }

            // ---- blk1: k01 rank-1 -> P, then scaled into acc blocks 1..3 ----
            {
                ldsm4t(bh0, bh1, bh2, bh3, cbase + 1 * 1536);
                ldsm4t(bl0, bl1, bl2, bl3, cbase + 1 * 1536 + 768);
#pragma unroll
                for (int mt = 0; mt < 2; mt++) {
                    float P[2][4];
#pragma unroll
                    for (int j = 0; j < 2; j++)
#pragma unroll
                        for (int r = 0; r < 4; r++) P[j][r] = 0.f;
                    mma16816(P[0], ah[mt][0][0], ah[mt][0][1], ah[mt][0][2], ah[mt][0][3], bh0, bh1);
                    mma16816(P[1], ah[mt][0][0], ah[mt][0][1], ah[mt][0][2], ah[mt][0][3], bh2, bh3);
                    mma16816(P[0], al[mt][0][0], al[mt][0][1], al[mt][0][2], al[mt][0][3], bh0, bh1);
                    mma16816(P[1], al[mt][0][0], al[mt][0][1], al[mt][0][2], al[mt][0][3], bh2, bh3);
                    mma16816(P[0], ah[mt][0][0], ah[mt][0][1], ah[mt][0][2], ah[mt][0][3], bl0, bl1);
                    mma16816(P[1], ah[mt][0][0], ah[mt][0][1], ah[mt][0][2], ah[mt][0][3], bl2, bl3);
#pragma unroll
                    for (int k = 0; k < 3; k++) {
                        const float sk = s[k];
#pragma unroll
                        for (int j = 0; j < 2; j++)
#pragma unroll
                            for (int r = 0; r < 4; r++)
                                acc[mt][2 * (k + 1) + j][r] += sk * P[j][r];
                    }
                }
            }

            // ---- blk2..4: k10 (A q=i+1 -> acc n-block 0) ----
#pragma unroll
            for (int i = 0; i < 3; i++) {
                ldsm4t(bh0, bh1, bh2, bh3, cbase + (2 + i) * 1536);
                ldsm4t(bl0, bl1, bl2, bl3, cbase + (2 + i) * 1536 + 768);
                const int q = i + 1;
#pragma unroll
                for (int mt = 0; mt < 2; mt++) {
                    mma16816(acc[mt][0], ah[mt][q][0], ah[mt][q][1], ah[mt][q][2], ah[mt][q][3], bh0, bh1);
                    mma16816(acc[mt][1], ah[mt][q][0], ah[mt][q][1], ah[mt][q][2], ah[mt][q][3], bh2, bh3);
                    mma16816(acc[mt][0], al[mt][q][0], al[mt][q][1], al[mt][q][2], al[mt][q][3], bh0, bh1);
                    mma16816(acc[mt][1], al[mt][q][0], al[mt][q][1], al[mt][q][2], al[mt][q][3], bh2, bh3);
                    mma16816(acc[mt][0], ah[mt][q][0], ah[mt][q][1], ah[mt][q][2], ah[mt][q][3], bl0, bl1);
                    mma16816(acc[mt][1], ah[mt][q][0], ah[mt][q][1], ah[mt][q][2], ah[mt][q][3], bl2, bl3);
                }
            }

            // ---- blk5: k11 diagonal, same B for all 3 i and both m-tiles ----
            {
                ldsm4t(bh0, bh1, bh2, bh3, cbase + 5 * 1536);
                ldsm4t(bl0, bl1, bl2, bl3, cbase + 5 * 1536 + 768);
#pragma unroll
                for (int mt = 0; mt < 2; mt++) {
#pragma unroll
                    for (int k = 0; k < 3; k++) {
                        const int q = k + 1;
                        float* d0 = acc[mt][2 * (k + 1)];
                        float* d1 = acc[mt][2 * (k + 1) + 1];
                        mma16816(d0, ah[mt][q][0], ah[mt][q][1], ah[mt][q][2], ah[mt][q][3], bh0, bh1);
                        mma16816(d1, ah[mt][q][0], ah[mt][q][1], ah[mt][q][2], ah[mt][q][3], bh2, bh3);
                        mma16816(d0, al[mt][q][0], al[mt][q][1], al[mt][q][2], al[mt][q][3], bh0, bh1);
                        mma16816(d1, al[mt][q][0], al[mt][q][1], al[mt][q][2], al[mt][q][3], bh2, bh3);
                        mma16816(d0, ah[mt][q][0], ah[mt][q][1], ah[mt][q][2], ah[mt][q][3], bl0, bl1);
                        mma16816(d1, ah[mt][q][0], ah[mt][q][1], ah[mt][q][2], ah[mt][q][3], bl2, bl3);
                    }
                }
            }
        }

        if (p + 1 < npl) CP_WAIT0();
        __syncthreads();
    }

    // ---- epilogue: direct global stores, un-permute cout ----
    const int g  = lane >> 2;
    const int cc = lane & 3;
    const int z  = zb + g;
#pragma unroll
    for (int mt = 0; mt < 2; mt++) {
        const int y = y0 + ysw * 2 + mt;
        float* ob = out + ((((size_t)b * 64) * 64 + x0) * 64 + y) * 64 + z;
#pragma unroll
        for (int nt = 0; nt < 8; nt++) {
            const int n0 = nt * 8 + 2 * cc;
            const int ch0 = (n0 < 16) ? n0 : (16 + 3 * ((n0 - 16) & 15) + ((n0 - 16) >> 4));
            const int n1 = n0 + 1;
            const int ch1 = (n1 < 16) ? n1 : (16 + 3 * ((n1 - 16) & 15) + ((n1 - 16) >> 4));
            float* p0 = ob + (size_t)ch0 * 262144;
            float* p1 = ob + (size_t)ch1 * 262144;
            p0[0] = acc[mt][nt][0];
            p1[0] = acc[mt][nt][1];
            p0[8] = acc[mt][nt][2];
            p1[8] = acc[mt][nt][3];
        }
    }
}

// ---------------------------------------------------------------------------
// Launch
// ---------------------------------------------------------------------------
extern "C" void kernel_launch(void* const* d_in, const int* in_sizes, int n_in,
                              void* d_out, int out_size)
{
    const float* x   = (const float*)d_in[0];
    const float* lw0 = (const float*)d_in[1];
    const float* lw1 = (const float*)d_in[2];
    const float* tp  = (const float*)d_in[3];
    float* out = (float*)d_out;

    xsplit<<<2 * 64 * 64, 256>>>(x);
    build_weights<<<125, 256>>>(lw0, lw1, tp);

    cudaFuncSetAttribute(conv_mma, cudaFuncAttributeMaxDynamicSharedMemorySize,
                         SM_TOT);
    conv_mma<<<2 * 64 * 16, 256, SM_TOT>>>(out);
}

// round 14
// speedup vs baseline: 1.5860x; 1.4845x over previous
#include <cuda_runtime.h>
#include <cuda_fp16.h>
#include <cstdint>

#define DIM 64

// Compact B blocks, fp16 hi/lo, built directly by build_weights:
//   [tap t=slab*5+c][blk 0..5][half hi/lo][16 rows x 48B (16 n*2B + pad)]
//   blk0=k00, blk1=base01, blk2..4=b10*sh[i], blk5=v11(diag)
__device__ __align__(16) unsigned char g_Bc[125 * 6 * 2 * 768];
// channel-last fp16 x (single precision level): [b][x][y][z][ci'] (PERMUTED)
__device__ __align__(128) __half g_xh[2ull * 64 * 64 * 64 * 64];
// 16B zero source for halo cp.async
__device__ __align__(16) float g_zero[4] = {0.f, 0.f, 0.f, 0.f};

// channel permutation: orig 16+3u+i  ->  16+16i+u ; identity below 16
__device__ __forceinline__ int perm_ch(int ci) {
    if (ci < 16) return ci;
    const int r = ci - 16;
    return 16 + (r % 3) * 16 + (r / 3);
}

// ---------------------------------------------------------------------------
// Kernel 1: build compact B blocks (fp16 hi/lo) straight from inputs
// ---------------------------------------------------------------------------
__global__ void build_weights(const float* __restrict__ lw0,
                              const float* __restrict__ lw1,
                              const float* __restrict__ tp)
{
    const int t  = blockIdx.x;            // 0..124, t = (a*5+bb)*5 + c
    const int a  = t / 25;
    const int b2 = (t / 5) % 5;
    const int c  = t % 5;

    const float lx = -1.f + 0.5f * (float)a;
    const float ly = -1.f + 0.5f * (float)b2;
    const float lz = -1.f + 0.5f * (float)c;
    const float d  = sqrtf(lx*lx + ly*ly + lz*lz);

    float ux = 0.f, uy = 0.f, uz = 0.f;
    if (d > 0.f) { ux = lx / d; uy = ly / d; uz = lz / d; }
    const float SQ3 = 1.7320508075688772f;
    const float s0 = SQ3 * uy, s1 = SQ3 * uz, s2 = SQ3 * ux;

    const float scale = cosf(3.14159265358979323846f * d) / 11.180339887498949f;
    float coef[5];
#pragma unroll
    for (int s = 0; s < 5; s++) {
        float u = (d - 0.25f * (float)s) / 0.25f;
        coef[s] = expf(-u * u) * (1.0f / 1.12f) * scale;
    }

    const int u_ = threadIdx.x >> 4;
    const int w_ = threadIdx.x & 15;
    const int m  = u_ * 16 + w_;

    float eA = 0.f, eB = 0.f, eC = 0.f, eD = 0.f;
#pragma unroll
    for (int s = 0; s < 5; s++) {
        const float cs = coef[s];
        eA += cs * tp[s * 1024 +   0 + m];
        eB += cs * tp[s * 1024 + 256 + m];
        eC += cs * tp[s * 1024 + 512 + m];
        eD += cs * tp[s * 1024 + 768 + m];
    }

    const float A0  = 0.17677669529663689f;   // sqrt(1/32)
    const float A1  = 0.30618621784789724f;   // sqrt(3/32)
    const float IS3 = 0.57735026918962576f;   // 1/sqrt(3)
    const float inv = 0.25f;
    const bool  center = (t == 62);           // (2,2,2)
    const float b10 = 0.1f * A0 * IS3 * eD;

    float blkv[6];
    blkv[0] = 0.1f * A0 * eA + (center ? inv * lw0[m] : 0.f);
    blkv[1] = 0.1f * A1 * IS3 * eB;
    blkv[2] = b10 * s0;
    blkv[3] = b10 * s1;
    blkv[4] = b10 * s2;
    blkv[5] = 0.1f * A1 * IS3 * eC + (center ? inv * lw1[m] : 0.f);

#pragma unroll
    for (int blk = 0; blk < 6; blk++) {
        const float v = blkv[blk];
        const __half h = __float2half(v);
        const __half l = __float2half(v - __half2float(h));
        const size_t off = ((size_t)(t * 6 + blk) * 2) * 768
                         + (size_t)u_ * 48 + (size_t)w_ * 2;
        *(__half*)(g_Bc + off)       = h;
        *(__half*)(g_Bc + off + 768) = l;
    }
}

// ---------------------------------------------------------------------------
// Kernel 2: transpose x -> channel-last (PERMUTED) fp16
// ---------------------------------------------------------------------------
__global__ void __launch_bounds__(256) xsplit(const float* __restrict__ x)
{
    __shared__ float s[64][65];
    const int gid = blockIdx.x;            // b*4096 + xx*64 + y
    const int y  = gid & 63;
    const int xx = (gid >> 6) & 63;
    const int b  = gid >> 12;
    const int tid = threadIdx.x;
    const int zz = tid & 63;
    const int cq = tid >> 6;               // 0..3

    const size_t sp = (size_t)(xx * 64 + y) * 64;
#pragma unroll
    for (int r = 0; r < 16; r++) {
        const int ci = cq * 16 + r;
        s[ci][zz] = x[(size_t)(b * 64 + ci) * 262144 + sp + zz];
    }
    __syncthreads();

    __half* oH = g_xh + (((size_t)(b * 64 + xx) * 64 + y) << 12);
    const int ci_w = tid & 63;
    const int cp   = perm_ch(ci_w);
#pragma unroll
    for (int r = 0; r < 16; r++) {
        const int z = cq * 16 + r;
        oH[z * 64 + cp] = __float2half(s[ci_w][z]);
    }
}

// ---------------------------------------------------------------------------
// PTX helpers (all base-target sm_80+ instructions)
// ---------------------------------------------------------------------------
__device__ __forceinline__ uint32_t smem_u32(const void* p) {
    uint32_t a;
    asm("{ .reg .u64 t; cvta.to.shared.u64 t, %1; cvt.u32.u64 %0, t; }"
        : "=r"(a) : "l"(p));
    return a;
}
__device__ __forceinline__ void ldsm4(uint32_t& r0, uint32_t& r1,
                                      uint32_t& r2, uint32_t& r3, uint32_t a) {
    asm volatile("ldmatrix.sync.aligned.m8n8.x4.shared.b16 {%0,%1,%2,%3}, [%4];"
                 : "=r"(r0), "=r"(r1), "=r"(r2), "=r"(r3) : "r"(a));
}
__device__ __forceinline__ void ldsm4t(uint32_t& r0, uint32_t& r1,
                                       uint32_t& r2, uint32_t& r3, uint32_t a) {
    asm volatile("ldmatrix.sync.aligned.m8n8.x4.trans.shared.b16 {%0,%1,%2,%3}, [%4];"
                 : "=r"(r0), "=r"(r1), "=r"(r2), "=r"(r3) : "r"(a));
}
__device__ __forceinline__ void mma16816(float* d, uint32_t a0, uint32_t a1,
                                         uint32_t a2, uint32_t a3,
                                         uint32_t b0, uint32_t b1) {
    asm volatile(
        "mma.sync.aligned.m16n8k16.row.col.f32.f16.f16.f32 "
        "{%0,%1,%2,%3}, {%4,%5,%6,%7}, {%8,%9}, {%0,%1,%2,%3};"
        : "+f"(d[0]), "+f"(d[1]), "+f"(d[2]), "+f"(d[3])
        : "r"(a0), "r"(a1), "r"(a2), "r"(a3), "r"(b0), "r"(b1));
}
__device__ __forceinline__ void cpa16(uint32_t dst, const void* src) {
    asm volatile("cp.async.cg.shared.global [%0], [%1], 16;"
                 :: "r"(dst), "l"(src));
}
#define CP_COMMIT() asm volatile("cp.async.commit_group;" ::: "memory")
#define CP_WAIT0()  asm volatile("cp.async.wait_group 0;" ::: "memory")

// ---------------------------------------------------------------------------
// SMEM map (bytes, within dynamic smem)
//   B: 2 bufs x 46080 (5c x 6blk x 2half x 768B)   =  92160
//   Input: 2 stages x 4 ys x 64 rows x 128B        =  65536
// ---------------------------------------------------------------------------
#define SM_B     0
#define SM_IN    92160
#define SM_ZERO  157696
#define SM_TOT   157824
#define PLANE_B  46080

// ---------------------------------------------------------------------------
// Kernel 3: mma.sync implicit-GEMM conv, fp16 2-term (Ah*Bh + Ah*Bl),
//           M=256 per CTA, structured blocks (R11/R13 layout).
// ---------------------------------------------------------------------------
__global__ void __launch_bounds__(256, 1)
conv_mma(float* __restrict__ out)
{
    extern __shared__ char smem[];
    const uint32_t sb = smem_u32(smem);
    const int tid  = threadIdx.x;
    const int wid  = tid >> 5;
    const int lane = tid & 31;

    const int gid = blockIdx.x;                  // 2*64*16 = 2048 CTAs
    const int y0  = (gid & 15) * 4;
    const int x0  = (gid >> 4) & 63;
    const int b   = gid >> 10;

    if (tid < 8)
        *(float4*)(smem + SM_ZERO + tid * 16) = make_float4(0.f, 0.f, 0.f, 0.f);

    // plane list (uniform across block)
    int pslab[25], pxi[25], pbb[25];
    int npl = 0;
#pragma unroll
    for (int a = 0; a < 5; a++) {
        const int xi = x0 + a - 2;
        if ((unsigned)xi >= 64u) continue;
#pragma unroll
        for (int bb = 0; bb < 5; bb++) {
            const int ylo = y0 + bb - 2;
            const int yhi = ylo + 3;
            if (yhi < 0 || ylo > 63) continue;
            pslab[npl] = a * 5 + bb;
            pxi[npl]   = xi;
            pbb[npl]   = bb;
            npl++;
        }
    }

    // per-warp / per-thread constants
    const int zb   = (wid & 3) * 16;
    const int ysw  = wid >> 2;                   // ys pair base = ysw*2
    const int mloc = (lane & 7) + ((lane >> 3) & 1) * 8;
    const int ksub = lane >> 4;
    const uint32_t zeroAddr = sb + SM_ZERO;
    const uint32_t bl_off = (uint32_t)(lane & 15) * 48u + (uint32_t)(lane >> 4) * 16u;
    float acc[2][8][4];
#pragma unroll
    for (int mt = 0; mt < 2; mt++)
#pragma unroll
        for (int nt = 0; nt < 8; nt++)
#pragma unroll
            for (int i = 0; i < 4; i++) acc[mt][nt][i] = 0.f;

    // staging lambdas -------------------------------------------------------
    auto stage_B = [&](int p, int buf) {
        const unsigned char* src = g_Bc + (size_t)pslab[p] * PLANE_B;
        const uint32_t dst0 = sb + SM_B + buf * PLANE_B;
#pragma unroll
        for (int i = 0; i < 12; i++) {
            const int id = tid + i * 256;        // 0..3071, guard at 2880
            if (id < PLANE_B / 16)
                cpa16(dst0 + id * 16, src + id * 16);
        }
    };
    auto stage_In = [&](int p, int stg) {
        const int xi = pxi[p], bb = pbb[p];
#pragma unroll
        for (int i = 0; i < 8; i++) {
            const int id   = tid + i * 256;      // 0..2047
            const int col  = id & 7;
            const int z    = (id >> 3) & 63;
            const int ys   = (id >> 9) & 3;
            const int yi   = y0 + ys + bb - 2;
            const bool ok  = (unsigned)yi < 64u;
            const void* src = ok
                ? (const void*)(g_xh + (((size_t)(b * 64 + xi) * 64 + yi) << 12)
                                + z * 64 + col * 8)
                : (const void*)g_zero;
            const uint32_t dst = sb + SM_IN + stg * 32768
                               + ys * 8192 + z * 128
                               + (((uint32_t)col * 16u) ^ (((uint32_t)z & 7u) << 4));
            cpa16(dst, src);
        }
    };

    // prologue
    stage_B(0, 0);
    stage_In(0, 0);
    CP_COMMIT();
    CP_WAIT0();
    __syncthreads();

#pragma unroll 1
    for (int p = 0; p < npl; p++) {
        if (p + 1 < npl) {
            stage_B(p + 1, (p + 1) & 1);
            stage_In(p + 1, (p + 1) & 1);
            CP_COMMIT();
        }

        const uint32_t Bb   = sb + SM_B + (p & 1) * PLANE_B;
        const uint32_t inSt = sb + SM_IN + (p & 1) * 32768;

        const int slab = pslab[p];
        const int pa   = slab / 5;
        const int pb   = slab - pa * 5;
        const float lx = -1.f + 0.5f * (float)pa;
        const float ly = -1.f + 0.5f * (float)pb;

        // ---- compute: 5 c-taps, structured blocks, 2 m-tiles per warp ----
#pragma unroll 1
        for (int c = 0; c < 5; c++) {
            const float lz = -1.f + 0.5f * (float)c;
            const float d2 = lx*lx + ly*ly + lz*lz;
            float s[3];
            if (d2 > 0.f) {
                const float ri = rsqrtf(d2) * 1.7320508075688772f;
                s[0] = ly * ri; s[1] = lz * ri; s[2] = lx * ri;
            } else { s[0] = s[1] = s[2] = 0.f; }

            // A fragments: 2 m-tiles x 4 q-blocks (fp16 hi only)
            const int zi = zb + mloc + c - 2;
            const bool vz = (unsigned)zi < 64u;
            const uint32_t jx   = ((uint32_t)zi & 7u) << 4;
            const uint32_t arow = (uint32_t)zi * 128u;
            uint32_t ah[2][4][4];
#pragma unroll
            for (int mt = 0; mt < 2; mt++) {
                const uint32_t inH = inSt + (ysw * 2 + mt) * 8192;
#pragma unroll
                for (int q = 0; q < 4; q++) {
                    const uint32_t acol = ((uint32_t)(q * 32 + ksub * 16)) ^ jx;
                    const uint32_t aH = vz ? (inH + arow + acol) : zeroAddr;
                    ldsm4(ah[mt][q][0], ah[mt][q][1], ah[mt][q][2], ah[mt][q][3], aH);
                }
            }

            const uint32_t cbase = Bb + (uint32_t)(c * 6 * 2) * 768u + bl_off;
            uint32_t bh0, bh1, bh2, bh3, bl0, bl1, bl2, bl3;

            // ---- blk0: k00 (A q=0 -> acc n-block 0) ----
            ldsm4t(bh0, bh1, bh2, bh3, cbase + 0 * 1536);
            ldsm4t(bl0, bl1, bl2, bl3, cbase + 0 * 1536 + 768);
#pragma unroll
            for (int mt = 0; mt < 2; mt++) {
                mma16816(acc[mt][0], ah[mt][0][0], ah[mt][0][1], ah[mt][0][2], ah[mt][0][3], bh0, bh1);
                mma16816(acc[mt][1], ah[mt][0][0], ah[mt][0][1], ah[mt][0][2], ah[mt][0][3], bh2, bh3);
                mma16816(acc[mt][0], ah[mt][0][0], ah[mt][0][1], ah[mt][0][2], ah[mt][0][3], bl0, bl1);
                mma16816(acc[mt][1], ah[mt][0][0], ah[mt][0][1], ah[mt][0][2], ah[mt][0][3], bl2, bl3);
            }

            // ---- blk1: k01 rank-1 -> P, then scaled into acc blocks 1..3 ----
            {
                ldsm4t(bh0, bh1, bh2, bh3, cbase + 1 * 1536);
                ldsm4t(bl0, bl1, bl2, bl3, cbase + 1 * 1536 + 768);
#pragma unroll
                for (int mt = 0; mt < 2; mt++) {
                    float P[2][4];
#pragma unroll
                    for (int j = 0; j < 2; j++)
#pragma unroll
                        for (int r = 0; r < 4; r++) P[j][r] = 0.f;
                    mma16816(P[0], ah[mt][0][0], ah[mt][0][1], ah[mt][0][2], ah[mt][0][3], bh0, bh1);
                    mma16816(P[1], ah[mt][0][0], ah[mt][0][1], ah[mt][0][2], ah[mt][0][3], bh2, bh3);
                    mma16816(P[0], ah[mt][0][0], ah[mt][0][1], ah[mt][0][2], ah[mt][0][3], bl0, bl1);
                    mma16816(P[1], ah[mt][0][0], ah[mt][0][1], ah[mt][0][2], ah[mt][0][3], bl2, bl3);
#pragma unroll
                    for (int k = 0; k < 3; k++) {
                        const float sk = s[k];
#pragma unroll
                        for (int j = 0; j < 2; j++)
#pragma unroll
                            for (int r = 0; r < 4; r++)
                                acc[mt][2 * (k + 1) + j][r] += sk * P[j][r];
                    }
                }
            }

            // ---- blk2..4: k10 (A q=i+1 -> acc n-block 0) ----
#pragma unroll
            for (int i = 0; i < 3; i++) {
                ldsm4t(bh0, bh1, bh2, bh3, cbase + (2 + i) * 1536);
                ldsm4t(bl0, bl1, bl2, bl3, cbase + (2 + i) * 1536 + 768);
                const int q = i + 1;
#pragma unroll
                for (int mt = 0; mt < 2; mt++) {
                    mma16816(acc[mt][0], ah[mt][q][0], ah[mt][q][1], ah[mt][q][2], ah[mt][q][3], bh0, bh1);
                    mma16816(acc[mt][1], ah[mt][q][0], ah[mt][q][1], ah[mt][q][2], ah[mt][q][3], bh2, bh3);
                    mma16816(acc[mt][0], ah[mt][q][0], ah[mt][q][1], ah[mt][q][2], ah[mt][q][3], bl0, bl1);
                    mma16816(acc[mt][1], ah[mt][q][0], ah[mt][q][1], ah[mt][q][2], ah[mt][q][3], bl2, bl3);
                }
            }

            // ---- blk5: k11 diagonal, same B for all 3 i and both m-tiles ----
            {
                ldsm4t(bh0, bh1, bh2, bh3, cbase + 5 * 1536);
                ldsm4t(bl0, bl1, bl2, bl3, cbase + 5 * 1536 + 768);
#pragma unroll
                for (int mt = 0; mt < 2; mt++) {
#pragma unroll
                    for (int k = 0; k < 3; k++) {
                        const int q = k + 1;
                        float* d0 = acc[mt][2 * (k + 1)];
                        float* d1 = acc[mt][2 * (k + 1) + 1];
                        mma16816(d0, ah[mt][q][0], ah[mt][q][1], ah[mt][q][2], ah[mt][q][3], bh0, bh1);
                        mma16816(d1, ah[mt][q][0], ah[mt][q][1], ah[mt][q][2], ah[mt][q][3], bh2, bh3);
                        mma16816(d0, ah[mt][q][0], ah[mt][q][1], ah[mt][q][2], ah[mt][q][3], bl0, bl1);
                        mma16816(d1, ah[mt][q][0], ah[mt][q][1], ah[mt][q][2], ah[mt][q][3], bl2, bl3);
                    }
                }
            }
        }

        if (p + 1 < npl) CP_WAIT0();
        __syncthreads();
    }

    // ---- epilogue: direct global stores, un-permute cout ----
    const int g  = lane >> 2;
    const int cc = lane & 3;
    const int z  = zb + g;
#pragma unroll
    for (int mt = 0; mt < 2; mt++) {
        const int y = y0 + ysw * 2 + mt;
        float* ob = out + ((((size_t)b * 64) * 64 + x0) * 64 + y) * 64 + z;
#pragma unroll
        for (int nt = 0; nt < 8; nt++) {
            const int n0 = nt * 8 + 2 * cc;
            const int ch0 = (n0 < 16) ? n0 : (16 + 3 * ((n0 - 16) & 15) + ((n0 - 16) >> 4));
            const int n1 = n0 + 1;
            const int ch1 = (n1 < 16) ? n1 : (16 + 3 * ((n1 - 16) & 15) + ((n1 - 16) >> 4));
            float* p0 = ob + (size_t)ch0 * 262144;
            float* p1 = ob + (size_t)ch1 * 262144;
            p0[0] = acc[mt][nt][0];
            p1[0] = acc[mt][nt][1];
            p0[8] = acc[mt][nt][2];
            p1[8] = acc[mt][nt][3];
        }
    }
}

// ---------------------------------------------------------------------------
// Launch
// ---------------------------------------------------------------------------
extern "C" void kernel_launch(void* const* d_in, const int* in_sizes, int n_in,
                              void* d_out, int out_size)
{
    const float* x   = (const float*)d_in[0];
    const float* lw0 = (const float*)d_in[1];
    const float* lw1 = (const float*)d_in[2];
    const float* tp  = (const float*)d_in[3];
    float* out = (float*)d_out;

    xsplit<<<2 * 64 * 64, 256>>>(x);
    build_weights<<<125, 256>>>(lw0, lw1, tp);

    cudaFuncSetAttribute(conv_mma, cudaFuncAttributeMaxDynamicSharedMemorySize,
                         SM_TOT);
    conv_mma<<<2 * 64 * 16, 256, SM_TOT>>>(out);
}

// round 15
// speedup vs baseline: 2.5253x; 1.5923x over previous
#include <cuda_runtime.h>
#include <cuda_fp16.h>
#include <cstdint>

#define DIM 64

// Compact B blocks, fp16 (single level), built directly by build_weights:
//   [tap t=slab*5+c][blk 0..5][16 rows x 48B (16 n*2B + pad)]
//   blk0=k00, blk1=base01, blk2..4=b10*sh[i], blk5=v11(diag)
__device__ __align__(16) unsigned char g_Bc[125 * 6 * 768];
// channel-last fp16 x: [b][x][y][z][ci'] (PERMUTED channels)
__device__ __align__(128) __half g_xh[2ull * 64 * 64 * 64 * 64];
// 16B zero source for halo cp.async
__device__ __align__(16) float g_zero[4] = {0.f, 0.f, 0.f, 0.f};

// channel permutation: orig 16+3u+i  ->  16+16i+u ; identity below 16
__device__ __forceinline__ int perm_ch(int ci) {
    if (ci < 16) return ci;
    const int r = ci - 16;
    return 16 + (r % 3) * 16 + (r / 3);
}

// ---------------------------------------------------------------------------
// Kernel 1: build compact B blocks (fp16) straight from inputs
// ---------------------------------------------------------------------------
__global__ void build_weights(const float* __restrict__ lw0,
                              const float* __restrict__ lw1,
                              const float* __restrict__ tp)
{
    const int t  = blockIdx.x;            // 0..124, t = (a*5+bb)*5 + c
    const int a  = t / 25;
    const int b2 = (t / 5) % 5;
    const int c  = t % 5;

    const float lx = -1.f + 0.5f * (float)a;
    const float ly = -1.f + 0.5f * (float)b2;
    const float lz = -1.f + 0.5f * (float)c;
    const float d  = sqrtf(lx*lx + ly*ly + lz*lz);

    float ux = 0.f, uy = 0.f, uz = 0.f;
    if (d > 0.f) { ux = lx / d; uy = ly / d; uz = lz / d; }
    const float SQ3 = 1.7320508075688772f;
    const float s0 = SQ3 * uy, s1 = SQ3 * uz, s2 = SQ3 * ux;

    const float scale = cosf(3.14159265358979323846f * d) / 11.180339887498949f;
    float coef[5];
#pragma unroll
    for (int s = 0; s < 5; s++) {
        float u = (d - 0.25f * (float)s) / 0.25f;
        coef[s] = expf(-u * u) * (1.0f / 1.12f) * scale;
    }

    const int u_ = threadIdx.x >> 4;
    const int w_ = threadIdx.x & 15;
    const int m  = u_ * 16 + w_;

    float eA = 0.f, eB = 0.f, eC = 0.f, eD = 0.f;
#pragma unroll
    for (int s = 0; s < 5; s++) {
        const float cs = coef[s];
        eA += cs * tp[s * 1024 +   0 + m];
        eB += cs * tp[s * 1024 + 256 + m];
        eC += cs * tp[s * 1024 + 512 + m];
        eD += cs * tp[s * 1024 + 768 + m];
    }

    const float A0  = 0.17677669529663689f;   // sqrt(1/32)
    const float A1  = 0.30618621784789724f;   // sqrt(3/32)
    const float IS3 = 0.57735026918962576f;   // 1/sqrt(3)
    const float inv = 0.25f;
    const bool  center = (t == 62);           // (2,2,2)
    const float b10 = 0.1f * A0 * IS3 * eD;

    float blkv[6];
    blkv[0] = 0.1f * A0 * eA + (center ? inv * lw0[m] : 0.f);
    blkv[1] = 0.1f * A1 * IS3 * eB;
    blkv[2] = b10 * s0;
    blkv[3] = b10 * s1;
    blkv[4] = b10 * s2;
    blkv[5] = 0.1f * A1 * IS3 * eC + (center ? inv * lw1[m] : 0.f);

#pragma unroll
    for (int blk = 0; blk < 6; blk++) {
        const size_t off = (size_t)(t * 6 + blk) * 768
                         + (size_t)u_ * 48 + (size_t)w_ * 2;
        *(__half*)(g_Bc + off) = __float2half(blkv[blk]);
    }
}

// ---------------------------------------------------------------------------
// Kernel 2: transpose x -> channel-last (PERMUTED) fp16
// ---------------------------------------------------------------------------
__global__ void __launch_bounds__(256) xsplit(const float* __restrict__ x)
{
    __shared__ float s[64][65];
    const int gid = blockIdx.x;            // b*4096 + xx*64 + y
    const int y  = gid & 63;
    const int xx = (gid >> 6) & 63;
    const int b  = gid >> 12;
    const int tid = threadIdx.x;
    const int zz = tid & 63;
    const int cq = tid >> 6;               // 0..3

    const size_t sp = (size_t)(xx * 64 + y) * 64;
#pragma unroll
    for (int r = 0; r < 16; r++) {
        const int ci = cq * 16 + r;
        s[ci][zz] = x[(size_t)(b * 64 + ci) * 262144 + sp + zz];
    }
    __syncthreads();

    __half* oH = g_xh + (((size_t)(b * 64 + xx) * 64 + y) << 12);
    const int ci_w = tid & 63;
    const int cp   = perm_ch(ci_w);
#pragma unroll
    for (int r = 0; r < 16; r++) {
        const int z = cq * 16 + r;
        oH[z * 64 + cp] = __float2half(s[ci_w][z]);
    }
}

// ---------------------------------------------------------------------------
// PTX helpers (all base-target sm_80+ instructions)
// ---------------------------------------------------------------------------
__device__ __forceinline__ uint32_t smem_u32(const void* p) {
    uint32_t a;
    asm("{ .reg .u64 t; cvta.to.shared.u64 t, %1; cvt.u32.u64 %0, t; }"
        : "=r"(a) : "l"(p));
    return a;
}
__device__ __forceinline__ void ldsm4(uint32_t& r0, uint32_t& r1,
                                      uint32_t& r2, uint32_t& r3, uint32_t a) {
    asm volatile("ldmatrix.sync.aligned.m8n8.x4.shared.b16 {%0,%1,%2,%3}, [%4];"
                 : "=r"(r0), "=r"(r1), "=r"(r2), "=r"(r3) : "r"(a));
}
__device__ __forceinline__ void ldsm4t(uint32_t& r0, uint32_t& r1,
                                       uint32_t& r2, uint32_t& r3, uint32_t a) {
    asm volatile("ldmatrix.sync.aligned.m8n8.x4.trans.shared.b16 {%0,%1,%2,%3}, [%4];"
                 : "=r"(r0), "=r"(r1), "=r"(r2), "=r"(r3) : "r"(a));
}
__device__ __forceinline__ void mma16816(float* d, uint32_t a0, uint32_t a1,
                                         uint32_t a2, uint32_t a3,
                                         uint32_t b0, uint32_t b1) {
    asm volatile(
        "mma.sync.aligned.m16n8k16.row.col.f32.f16.f16.f32 "
        "{%0,%1,%2,%3}, {%4,%5,%6,%7}, {%8,%9}, {%0,%1,%2,%3};"
        : "+f"(d[0]), "+f"(d[1]), "+f"(d[2]), "+f"(d[3])
        : "r"(a0), "r"(a1), "r"(a2), "r"(a3), "r"(b0), "r"(b1));
}
__device__ __forceinline__ void cpa16(uint32_t dst, const void* src) {
    asm volatile("cp.async.cg.shared.global [%0], [%1], 16;"
                 :: "r"(dst), "l"(src));
}
#define CP_COMMIT() asm volatile("cp.async.commit_group;" ::: "memory")
#define CP_WAIT0()  asm volatile("cp.async.wait_group 0;" ::: "memory")

// ---------------------------------------------------------------------------
// SMEM map (bytes, within dynamic smem)
//   B: 2 bufs x 23040 (5c x 6blk x 768B)           =  46080
//   Input: 2 stages x 4 ys x 64 rows x 128B        =  65536
// ---------------------------------------------------------------------------
#define SM_B     0
#define SM_IN    46080
#define SM_ZERO  111616
#define SM_TOT   111744
#define PLANE_B  23040

// ---------------------------------------------------------------------------
// Kernel 3: mma.sync implicit-GEMM conv, pure fp16 single-term,
//           M=256 per CTA, structured blocks (R13/R14 layout).
// ---------------------------------------------------------------------------
__global__ void __launch_bounds__(256, 1)
conv_mma(float* __restrict__ out)
{
    extern __shared__ char smem[];
    const uint32_t sb = smem_u32(smem);
    const int tid  = threadIdx.x;
    const int wid  = tid >> 5;
    const int lane = tid & 31;

    const int gid = blockIdx.x;                  // 2*64*16 = 2048 CTAs
    const int y0  = (gid & 15) * 4;
    const int x0  = (gid >> 4) & 63;
    const int b   = gid >> 10;

    if (tid < 8)
        *(float4*)(smem + SM_ZERO + tid * 16) = make_float4(0.f, 0.f, 0.f, 0.f);

    // plane list (uniform across block)
    int pslab[25], pxi[25], pbb[25];
    int npl = 0;
#pragma unroll
    for (int a = 0; a < 5; a++) {
        const int xi = x0 + a - 2;
        if ((unsigned)xi >= 64u) continue;
#pragma unroll
        for (int bb = 0; bb < 5; bb++) {
            const int ylo = y0 + bb - 2;
            const int yhi = ylo + 3;
            if (yhi < 0 || ylo > 63) continue;
            pslab[npl] = a * 5 + bb;
            pxi[npl]   = xi;
            pbb[npl]   = bb;
            npl++;
        }
    }

    // per-warp / per-thread constants
    const int zb   = (wid & 3) * 16;
    const int ysw  = wid >> 2;                   // ys pair base = ysw*2
    const int mloc = (lane & 7) + ((lane >> 3) & 1) * 8;
    const int ksub = lane >> 4;
    const uint32_t zeroAddr = sb + SM_ZERO;
    const uint32_t bl_off = (uint32_t)(lane & 15) * 48u + (uint32_t)(lane >> 4) * 16u;
    float acc[2][8][4];
#pragma unroll
    for (int mt = 0; mt < 2; mt++)
#pragma unroll
        for (int nt = 0; nt < 8; nt++)
#pragma unroll
            for (int i = 0; i < 4; i++) acc[mt][nt][i] = 0.f;

    // staging lambdas -------------------------------------------------------
    auto stage_B = [&](int p, int buf) {
        const unsigned char* src = g_Bc + (size_t)pslab[p] * PLANE_B;
        const uint32_t dst0 = sb + SM_B + buf * PLANE_B;
#pragma unroll
        for (int i = 0; i < 6; i++) {
            const int id = tid + i * 256;        // 0..1535, guard at 1440
            if (id < PLANE_B / 16)
                cpa16(dst0 + id * 16, src + id * 16);
        }
    };
    auto stage_In = [&](int p, int stg) {
        const int xi = pxi[p], bb = pbb[p];
#pragma unroll
        for (int i = 0; i < 8; i++) {
            const int id   = tid + i * 256;      // 0..2047
            const int col  = id & 7;
            const int z    = (id >> 3) & 63;
            const int ys   = (id >> 9) & 3;
            const int yi   = y0 + ys + bb - 2;
            const bool ok  = (unsigned)yi < 64u;
            const void* src = ok
                ? (const void*)(g_xh + (((size_t)(b * 64 + xi) * 64 + yi) << 12)
                                + z * 64 + col * 8)
                : (const void*)g_zero;
            const uint32_t dst = sb + SM_IN + stg * 32768
                               + ys * 8192 + z * 128
                               + (((uint32_t)col * 16u) ^ (((uint32_t)z & 7u) << 4));
            cpa16(dst, src);
        }
    };

    // prologue
    stage_B(0, 0);
    stage_In(0, 0);
    CP_COMMIT();
    CP_WAIT0();
    __syncthreads();

#pragma unroll 1
    for (int p = 0; p < npl; p++) {
        if (p + 1 < npl) {
            stage_B(p + 1, (p + 1) & 1);
            stage_In(p + 1, (p + 1) & 1);
            CP_COMMIT();
        }

        const uint32_t Bb   = sb + SM_B + (p & 1) * PLANE_B;
        const uint32_t inSt = sb + SM_IN + (p & 1) * 32768;

        const int slab = pslab[p];
        const int pa   = slab / 5;
        const int pb   = slab - pa * 5;
        const float lx = -1.f + 0.5f * (float)pa;
        const float ly = -1.f + 0.5f * (float)pb;

        // ---- compute: 5 c-taps, structured blocks, 2 m-tiles per warp ----
#pragma unroll 1
        for (int c = 0; c < 5; c++) {
            const float lz = -1.f + 0.5f * (float)c;
            const float d2 = lx*lx + ly*ly + lz*lz;
            float s[3];
            if (d2 > 0.f) {
                const float ri = rsqrtf(d2) * 1.7320508075688772f;
                s[0] = ly * ri; s[1] = lz * ri; s[2] = lx * ri;
            } else { s[0] = s[1] = s[2] = 0.f; }

            // A fragments: 2 m-tiles x 4 q-blocks (fp16)
            const int zi = zb + mloc + c - 2;
            const bool vz = (unsigned)zi < 64u;
            const uint32_t jx   = ((uint32_t)zi & 7u) << 4;
            const uint32_t arow = (uint32_t)zi * 128u;
            uint32_t ah[2][4][4];
#pragma unroll
            for (int mt = 0; mt < 2; mt++) {
                const uint32_t inH = inSt + (ysw * 2 + mt) * 8192;
#pragma unroll
                for (int q = 0; q < 4; q++) {
                    const uint32_t acol = ((uint32_t)(q * 32 + ksub * 16)) ^ jx;
                    const uint32_t aH = vz ? (inH + arow + acol) : zeroAddr;
                    ldsm4(ah[mt][q][0], ah[mt][q][1], ah[mt][q][2], ah[mt][q][3], aH);
                }
            }

            const uint32_t cbase = Bb + (uint32_t)(c * 6) * 768u + bl_off;
            uint32_t bh0, bh1, bh2, bh3;

            // ---- blk0: k00 (A q=0 -> acc n-block 0) ----
            ldsm4t(bh0, bh1, bh2, bh3, cbase + 0 * 768);
#pragma unroll
            for (int mt = 0; mt < 2; mt++) {
                mma16816(acc[mt][0], ah[mt][0][0], ah[mt][0][1], ah[mt][0][2], ah[mt][0][3], bh0, bh1);
                mma16816(acc[mt][1], ah[mt][0][0], ah[mt][0][1], ah[mt][0][2], ah[mt][0][3], bh2, bh3);
            }

            // ---- blk1: k01 rank-1 -> P, then scaled into acc blocks 1..3 ----
            {
                ldsm4t(bh0, bh1, bh2, bh3, cbase + 1 * 768);
#pragma unroll
                for (int mt = 0; mt < 2; mt++) {
                    float P[2][4];
#pragma unroll
                    for (int j = 0; j < 2; j++)
#pragma unroll
                        for (int r = 0; r < 4; r++) P[j][r] = 0.f;
                    mma16816(P[0], ah[mt][0][0], ah[mt][0][1], ah[mt][0][2], ah[mt][0][3], bh0, bh1);
                    mma16816(P[1], ah[mt][0][0], ah[mt][0][1], ah[mt][0][2], ah[mt][0][3], bh2, bh3);
#pragma unroll
                    for (int k = 0; k < 3; k++) {
                        const float sk = s[k];
#pragma unroll
                        for (int j = 0; j < 2; j++)
#pragma unroll
                            for (int r = 0; r < 4; r++)
                                acc[mt][2 * (k + 1) + j][r] += sk * P[j][r];
                    }
                }
            }

            // ---- blk2..4: k10 (A q=i+1 -> acc n-block 0) ----
#pragma unroll
            for (int i = 0; i < 3; i++) {
                ldsm4t(bh0, bh1, bh2, bh3, cbase + (2 + i) * 768);
                const int q = i + 1;
#pragma unroll
                for (int mt = 0; mt < 2; mt++) {
                    mma16816(acc[mt][0], ah[mt][q][0], ah[mt][q][1], ah[mt][q][2], ah[mt][q][3], bh0, bh1);
                    mma16816(acc[mt][1], ah[mt][q][0], ah[mt][q][1], ah[mt][q][2], ah[mt][q][3], bh2, bh3);
                }
            }

            // ---- blk5: k11 diagonal, same B for all 3 i and both m-tiles ----
            {
                ldsm4t(bh0, bh1, bh2, bh3, cbase + 5 * 768);
#pragma unroll
                for (int mt = 0; mt < 2; mt++) {
#pragma unroll
                    for (int k = 0; k < 3; k++) {
                        const int q = k + 1;
                        float* d0 = acc[mt][2 * (k + 1)];
                        float* d1 = acc[mt][2 * (k + 1) + 1];
                        mma16816(d0, ah[mt][q][0], ah[mt][q][1], ah[mt][q][2], ah[mt][q][3], bh0, bh1);
                        mma16816(d1, ah[mt][q][0], ah[mt][q][1], ah[mt][q][2], ah[mt][q][3], bh2, bh3);
                    }
                }
            }
        }

        if (p + 1 < npl) CP_WAIT0();
        __syncthreads();
    }

    // ---- epilogue: direct global stores, un-permute cout ----
    const int g  = lane >> 2;
    const int cc = lane & 3;
    const int z  = zb + g;
#pragma unroll
    for (int mt = 0; mt < 2; mt++) {
        const int y = y0 + ysw * 2 + mt;
        float* ob = out + ((((size_t)b * 64) * 64 + x0) * 64 + y) * 64 + z;
#pragma unroll
        for (int nt = 0; nt < 8; nt++) {
            const int n0 = nt * 8 + 2 * cc;
            const int ch0 = (n0 < 16) ? n0 : (16 + 3 * ((n0 - 16) & 15) + ((n0 - 16) >> 4));
            const int n1 = n0 + 1;
            const int ch1 = (n1 < 16) ? n1 : (16 + 3 * ((n1 - 16) & 15) + ((n1 - 16) >> 4));
            float* p0 = ob + (size_t)ch0 * 262144;
            float* p1 = ob + (size_t)ch1 * 262144;
            p0[0] = acc[mt][nt][0];
            p1[0] = acc[mt][nt][1];
            p0[8] = acc[mt][nt][2];
            p1[8] = acc[mt][nt][3];
        }
    }
}

// ---------------------------------------------------------------------------
// Launch
// ---------------------------------------------------------------------------
extern "C" void kernel_launch(void* const* d_in, const int* in_sizes, int n_in,
                              void* d_out, int out_size)
{
    const float* x   = (const float*)d_in[0];
    const float* lw0 = (const float*)d_in[1];
    const float* lw1 = (const float*)d_in[2];
    const float* tp  = (const float*)d_in[3];
    float* out = (float*)d_out;

    xsplit<<<2 * 64 * 64, 256>>>(x);
    build_weights<<<125, 256>>>(lw0, lw1, tp);

    cudaFuncSetAttribute(conv_mma, cudaFuncAttributeMaxDynamicSharedMemorySize,
                         SM_TOT);
    conv_mma<<<2 * 64 * 16, 256, SM_TOT>>>(out);
}

// round 16
// speedup vs baseline: 2.6348x; 1.0434x over previous
#include <cuda_runtime.h>
#include <cuda_fp16.h>
#include <cstdint>

#define DIM 64

// Compact B blocks, fp16, built directly by build_weights:
//   [tap t=slab*5+c][blk 0..5][16 rows x 48B (16 n*2B + pad)]
//   blk0=k00, blk1=base01, blk2..4=b10*sh[i], blk5=v11(diag)
__device__ __align__(16) unsigned char g_Bc[125 * 6 * 768];
// channel-last fp16 x: [b][x][y][z][ci'] (PERMUTED channels)
__device__ __align__(128) __half g_xh[2ull * 64 * 64 * 64 * 64];
// 16B zero source for halo cp.async
__device__ __align__(16) float g_zero[4] = {0.f, 0.f, 0.f, 0.f};

// channel permutation: orig 16+3u+i  ->  16+16i+u ; identity below 16
__device__ __forceinline__ int perm_ch(int ci) {
    if (ci < 16) return ci;
    const int r = ci - 16;
    return 16 + (r % 3) * 16 + (r / 3);
}

// ---------------------------------------------------------------------------
// Kernel 1: build compact B blocks (fp16) straight from inputs
// ---------------------------------------------------------------------------
__global__ void build_weights(const float* __restrict__ lw0,
                              const float* __restrict__ lw1,
                              const float* __restrict__ tp)
{
    const int t  = blockIdx.x;            // 0..124, t = (a*5+bb)*5 + c
    const int a  = t / 25;
    const int b2 = (t / 5) % 5;
    const int c  = t % 5;

    const float lx = -1.f + 0.5f * (float)a;
    const float ly = -1.f + 0.5f * (float)b2;
    const float lz = -1.f + 0.5f * (float)c;
    const float d  = sqrtf(lx*lx + ly*ly + lz*lz);

    float ux = 0.f, uy = 0.f, uz = 0.f;
    if (d > 0.f) { ux = lx / d; uy = ly / d; uz = lz / d; }
    const float SQ3 = 1.7320508075688772f;
    const float s0 = SQ3 * uy, s1 = SQ3 * uz, s2 = SQ3 * ux;

    const float scale = cosf(3.14159265358979323846f * d) / 11.180339887498949f;
    float coef[5];
#pragma unroll
    for (int s = 0; s < 5; s++) {
        float u = (d - 0.25f * (float)s) / 0.25f;
        coef[s] = expf(-u * u) * (1.0f / 1.12f) * scale;
    }

    const int u_ = threadIdx.x >> 4;
    const int w_ = threadIdx.x & 15;
    const int m  = u_ * 16 + w_;

    float eA = 0.f, eB = 0.f, eC = 0.f, eD = 0.f;
#pragma unroll
    for (int s = 0; s < 5; s++) {
        const float cs = coef[s];
        eA += cs * tp[s * 1024 +   0 + m];
        eB += cs * tp[s * 1024 + 256 + m];
        eC += cs * tp[s * 1024 + 512 + m];
        eD += cs * tp[s * 1024 + 768 + m];
    }

    const float A0  = 0.17677669529663689f;   // sqrt(1/32)
    const float A1  = 0.30618621784789724f;   // sqrt(3/32)
    const float IS3 = 0.57735026918962576f;   // 1/sqrt(3)
    const float inv = 0.25f;
    const bool  center = (t == 62);           // (2,2,2)
    const float b10 = 0.1f * A0 * IS3 * eD;

    float blkv[6];
    blkv[0] = 0.1f * A0 * eA + (center ? inv * lw0[m] : 0.f);
    blkv[1] = 0.1f * A1 * IS3 * eB;
    blkv[2] = b10 * s0;
    blkv[3] = b10 * s1;
    blkv[4] = b10 * s2;
    blkv[5] = 0.1f * A1 * IS3 * eC + (center ? inv * lw1[m] : 0.f);

#pragma unroll
    for (int blk = 0; blk < 6; blk++) {
        const size_t off = (size_t)(t * 6 + blk) * 768
                         + (size_t)u_ * 48 + (size_t)w_ * 2;
        *(__half*)(g_Bc + off) = __float2half(blkv[blk]);
    }
}

// ---------------------------------------------------------------------------
// Kernel 2: transpose x -> channel-last (PERMUTED) fp16
// ---------------------------------------------------------------------------
__global__ void __launch_bounds__(256) xsplit(const float* __restrict__ x)
{
    __shared__ float s[64][65];
    const int gid = blockIdx.x;            // b*4096 + xx*64 + y
    const int y  = gid & 63;
    const int xx = (gid >> 6) & 63;
    const int b  = gid >> 12;
    const int tid = threadIdx.x;
    const int zz = tid & 63;
    const int cq = tid >> 6;               // 0..3

    const size_t sp = (size_t)(xx * 64 + y) * 64;
#pragma unroll
    for (int r = 0; r < 16; r++) {
        const int ci = cq * 16 + r;
        s[ci][zz] = x[(size_t)(b * 64 + ci) * 262144 + sp + zz];
    }
    __syncthreads();

    __half* oH = g_xh + (((size_t)(b * 64 + xx) * 64 + y) << 12);
    const int ci_w = tid & 63;
    const int cp   = perm_ch(ci_w);
#pragma unroll
    for (int r = 0; r < 16; r++) {
        const int z = cq * 16 + r;
        oH[z * 64 + cp] = __float2half(s[ci_w][z]);
    }
}

// ---------------------------------------------------------------------------
// PTX helpers (all base-target sm_80+ instructions)
// ---------------------------------------------------------------------------
__device__ __forceinline__ uint32_t smem_u32(const void* p) {
    uint32_t a;
    asm("{ .reg .u64 t; cvta.to.shared.u64 t, %1; cvt.u32.u64 %0, t; }"
        : "=r"(a) : "l"(p));
    return a;
}
__device__ __forceinline__ void ldsm4(uint32_t& r0, uint32_t& r1,
                                      uint32_t& r2, uint32_t& r3, uint32_t a) {
    asm volatile("ldmatrix.sync.aligned.m8n8.x4.shared.b16 {%0,%1,%2,%3}, [%4];"
                 : "=r"(r0), "=r"(r1), "=r"(r2), "=r"(r3) : "r"(a));
}
__device__ __forceinline__ void ldsm4t(uint32_t& r0, uint32_t& r1,
                                       uint32_t& r2, uint32_t& r3, uint32_t a) {
    asm volatile("ldmatrix.sync.aligned.m8n8.x4.trans.shared.b16 {%0,%1,%2,%3}, [%4];"
                 : "=r"(r0), "=r"(r1), "=r"(r2), "=r"(r3) : "r"(a));
}
__device__ __forceinline__ void mma16816(float* d, uint32_t a0, uint32_t a1,
                                         uint32_t a2, uint32_t a3,
                                         uint32_t b0, uint32_t b1) {
    asm volatile(
        "mma.sync.aligned.m16n8k16.row.col.f32.f16.f16.f32 "
        "{%0,%1,%2,%3}, {%4,%5,%6,%7}, {%8,%9}, {%0,%1,%2,%3};"
        : "+f"(d[0]), "+f"(d[1]), "+f"(d[2]), "+f"(d[3])
        : "r"(a0), "r"(a1), "r"(a2), "r"(a3), "r"(b0), "r"(b1));
}
__device__ __forceinline__ void cpa16(uint32_t dst, const void* src) {
    asm volatile("cp.async.cg.shared.global [%0], [%1], 16;"
                 :: "r"(dst), "l"(src));
}
#define CP_COMMIT() asm volatile("cp.async.commit_group;" ::: "memory")
#define CP_WAIT0()  asm volatile("cp.async.wait_group 0;" ::: "memory")

// ---------------------------------------------------------------------------
// SMEM map (bytes, within dynamic smem)
//   B: 2 bufs x 23040 (5c x 6blk x 768B)           =  46080
//   Input: 2 stages x 4 ys x 64 rows x 128B        =  65536
// ---------------------------------------------------------------------------
#define SM_B     0
#define SM_IN    46080
#define SM_ZERO  111616
#define SM_TOT   111744
#define PLANE_B  23040

// ---------------------------------------------------------------------------
// Kernel 3: mma.sync implicit-GEMM conv, pure fp16, M=256 per CTA,
//           register-dieted per-q A loads, 2 CTAs/SM.
// ---------------------------------------------------------------------------
__global__ void __launch_bounds__(256, 2)
conv_mma(float* __restrict__ out)
{
    extern __shared__ char smem[];
    const uint32_t sb = smem_u32(smem);
    const int tid  = threadIdx.x;
    const int wid  = tid >> 5;
    const int lane = tid & 31;

    const int gid = blockIdx.x;                  // 2*64*16 = 2048 CTAs
    const int y0  = (gid & 15) * 4;
    const int x0  = (gid >> 4) & 63;
    const int b   = gid >> 10;

    if (tid < 8)
        *(float4*)(smem + SM_ZERO + tid * 16) = make_float4(0.f, 0.f, 0.f, 0.f);

    // plane list (uniform across block)
    int pslab[25], pxi[25], pbb[25];
    int npl = 0;
#pragma unroll
    for (int a = 0; a < 5; a++) {
        const int xi = x0 + a - 2;
        if ((unsigned)xi >= 64u) continue;
#pragma unroll
        for (int bb = 0; bb < 5; bb++) {
            const int ylo = y0 + bb - 2;
            const int yhi = ylo + 3;
            if (yhi < 0 || ylo > 63) continue;
            pslab[npl] = a * 5 + bb;
            pxi[npl]   = xi;
            pbb[npl]   = bb;
            npl++;
        }
    }

    // per-warp / per-thread constants
    const int zb   = (wid & 3) * 16;
    const int ysw  = wid >> 2;                   // ys pair base = ysw*2
    const int mloc = (lane & 7) + ((lane >> 3) & 1) * 8;
    const int ksub = lane >> 4;
    const uint32_t zeroAddr = sb + SM_ZERO;
    const uint32_t bl_off = (uint32_t)(lane & 15) * 48u + (uint32_t)(lane >> 4) * 16u;
    float acc[2][8][4];
#pragma unroll
    for (int mt = 0; mt < 2; mt++)
#pragma unroll
        for (int nt = 0; nt < 8; nt++)
#pragma unroll
            for (int i = 0; i < 4; i++) acc[mt][nt][i] = 0.f;

    // staging lambdas -------------------------------------------------------
    auto stage_B = [&](int p, int buf) {
        const unsigned char* src = g_Bc + (size_t)pslab[p] * PLANE_B;
        const uint32_t dst0 = sb + SM_B + buf * PLANE_B;
#pragma unroll
        for (int i = 0; i < 6; i++) {
            const int id = tid + i * 256;        // 0..1535, guard at 1440
            if (id < PLANE_B / 16)
                cpa16(dst0 + id * 16, src + id * 16);
        }
    };
    auto stage_In = [&](int p, int stg) {
        const int xi = pxi[p], bb = pbb[p];
#pragma unroll
        for (int i = 0; i < 8; i++) {
            const int id   = tid + i * 256;      // 0..2047
            const int col  = id & 7;
            const int z    = (id >> 3) & 63;
            const int ys   = (id >> 9) & 3;
            const int yi   = y0 + ys + bb - 2;
            const bool ok  = (unsigned)yi < 64u;
            const void* src = ok
                ? (const void*)(g_xh + (((size_t)(b * 64 + xi) * 64 + yi) << 12)
                                + z * 64 + col * 8)
                : (const void*)g_zero;
            const uint32_t dst = sb + SM_IN + stg * 32768
                               + ys * 8192 + z * 128
                               + (((uint32_t)col * 16u) ^ (((uint32_t)z & 7u) << 4));
            cpa16(dst, src);
        }
    };

    // prologue
    stage_B(0, 0);
    stage_In(0, 0);
    CP_COMMIT();
    CP_WAIT0();
    __syncthreads();

#pragma unroll 1
    for (int p = 0; p < npl; p++) {
        if (p + 1 < npl) {
            stage_B(p + 1, (p + 1) & 1);
            stage_In(p + 1, (p + 1) & 1);
            CP_COMMIT();
        }

        const uint32_t Bb   = sb + SM_B + (p & 1) * PLANE_B;
        const uint32_t inSt = sb + SM_IN + (p & 1) * 32768;

        const int slab = pslab[p];
        const int pa   = slab / 5;
        const int pb   = slab - pa * 5;
        const float lx = -1.f + 0.5f * (float)pa;
        const float ly = -1.f + 0.5f * (float)pb;

        // ---- compute: 5 c-taps, per-q A loads (register diet) ----
#pragma unroll 1
        for (int c = 0; c < 5; c++) {
            const float lz = -1.f + 0.5f * (float)c;
            const float d2 = lx*lx + ly*ly + lz*lz;
            float s[3];
            if (d2 > 0.f) {
                const float ri = rsqrtf(d2) * 1.7320508075688772f;
                s[0] = ly * ri; s[1] = lz * ri; s[2] = lx * ri;
            } else { s[0] = s[1] = s[2] = 0.f; }

            const int zi = zb + mloc + c - 2;
            const bool vz = (unsigned)zi < 64u;
            const uint32_t jx   = ((uint32_t)zi & 7u) << 4;
            const uint32_t arow = (uint32_t)zi * 128u;
            const uint32_t cbase = Bb + (uint32_t)(c * 6) * 768u + bl_off;

            // blk5 B fragment (persists across k loop)
            uint32_t b50, b51, b52, b53;
            ldsm4t(b50, b51, b52, b53, cbase + 5 * 768);

            uint32_t a[2][4];     // reused per q
            uint32_t t0, t1, t2, t3;

            // ---- q=0: blk0 (k00) + blk1 (k01 rank-1) ----
            {
                const uint32_t acol = ((uint32_t)(ksub * 16)) ^ jx;
#pragma unroll
                for (int mt = 0; mt < 2; mt++) {
                    const uint32_t inH = inSt + (ysw * 2 + mt) * 8192;
                    const uint32_t aA = vz ? (inH + arow + acol) : zeroAddr;
                    ldsm4(a[mt][0], a[mt][1], a[mt][2], a[mt][3], aA);
                }
                ldsm4t(t0, t1, t2, t3, cbase + 0 * 768);
#pragma unroll
                for (int mt = 0; mt < 2; mt++) {
                    mma16816(acc[mt][0], a[mt][0], a[mt][1], a[mt][2], a[mt][3], t0, t1);
                    mma16816(acc[mt][1], a[mt][0], a[mt][1], a[mt][2], a[mt][3], t2, t3);
                }
                ldsm4t(t0, t1, t2, t3, cbase + 1 * 768);
#pragma unroll
                for (int mt = 0; mt < 2; mt++) {
                    float P[2][4];
#pragma unroll
                    for (int j = 0; j < 2; j++)
#pragma unroll
                        for (int r = 0; r < 4; r++) P[j][r] = 0.f;
                    mma16816(P[0], a[mt][0], a[mt][1], a[mt][2], a[mt][3], t0, t1);
                    mma16816(P[1], a[mt][0], a[mt][1], a[mt][2], a[mt][3], t2, t3);
#pragma unroll
                    for (int k = 0; k < 3; k++) {
                        const float sk = s[k];
#pragma unroll
                        for (int j = 0; j < 2; j++)
#pragma unroll
                            for (int r = 0; r < 4; r++)
                                acc[mt][2 * (k + 1) + j][r] += sk * P[j][r];
                    }
                }
            }

            // ---- q=1..3: blk2..4 (k10) + blk5 (diag) ----
#pragma unroll
            for (int k = 0; k < 3; k++) {
                const int q = k + 1;
                const uint32_t acol = ((uint32_t)(q * 32 + ksub * 16)) ^ jx;
#pragma unroll
                for (int mt = 0; mt < 2; mt++) {
                    const uint32_t inH = inSt + (ysw * 2 + mt) * 8192;
                    const uint32_t aA = vz ? (inH + arow + acol) : zeroAddr;
                    ldsm4(a[mt][0], a[mt][1], a[mt][2], a[mt][3], aA);
                }
                ldsm4t(t0, t1, t2, t3, cbase + (2 + k) * 768);
#pragma unroll
                for (int mt = 0; mt < 2; mt++) {
                    mma16816(acc[mt][0], a[mt][0], a[mt][1], a[mt][2], a[mt][3], t0, t1);
                    mma16816(acc[mt][1], a[mt][0], a[mt][1], a[mt][2], a[mt][3], t2, t3);
                    mma16816(acc[mt][2 * (k + 1)],     a[mt][0], a[mt][1], a[mt][2], a[mt][3], b50, b51);
                    mma16816(acc[mt][2 * (k + 1) + 1], a[mt][0], a[mt][1], a[mt][2], a[mt][3], b52, b53);
                }
            }
        }

        if (p + 1 < npl) CP_WAIT0();
        __syncthreads();
    }

    // ---- epilogue: direct global stores, un-permute cout ----
    const int g  = lane >> 2;
    const int cc = lane & 3;
    const int z  = zb + g;
#pragma unroll
    for (int mt = 0; mt < 2; mt++) {
        const int y = y0 + ysw * 2 + mt;
        float* ob = out + ((((size_t)b * 64) * 64 + x0) * 64 + y) * 64 + z;
#pragma unroll
        for (int nt = 0; nt < 8; nt++) {
            const int n0 = nt * 8 + 2 * cc;
            const int ch0 = (n0 < 16) ? n0 : (16 + 3 * ((n0 - 16) & 15) + ((n0 - 16) >> 4));
            const int n1 = n0 + 1;
            const int ch1 = (n1 < 16) ? n1 : (16 + 3 * ((n1 - 16) & 15) + ((n1 - 16) >> 4));
            float* p0 = ob + (size_t)ch0 * 262144;
            float* p1 = ob + (size_t)ch1 * 262144;
            p0[0] = acc[mt][nt][0];
            p1[0] = acc[mt][nt][1];
            p0[8] = acc[mt][nt][2];
            p1[8] = acc[mt][nt][3];
        }
    }
}

// ---------------------------------------------------------------------------
// Launch
// ---------------------------------------------------------------------------
extern "C" void kernel_launch(void* const* d_in, const int* in_sizes, int n_in,
                              void* d_out, int out_size)
{
    const float* x   = (const float*)d_in[0];
    const float* lw0 = (const float*)d_in[1];
    const float* lw1 = (const float*)d_in[2];
    const float* tp  = (const float*)d_in[3];
    float* out = (float*)d_out;

    xsplit<<<2 * 64 * 64, 256>>>(x);
    build_weights<<<125, 256>>>(lw0, lw1, tp);

    cudaFuncSetAttribute(conv_mma, cudaFuncAttributeMaxDynamicSharedMemorySize,
                         SM_TOT);
    conv_mma<<<2 * 64 * 16, 256, SM_TOT>>>(out);
}

// round 17
// speedup vs baseline: 2.8991x; 1.1003x over previous
#include <cuda_runtime.h>
#include <cuda_fp16.h>
#include <cstdint>

#define DIM 64

// Compact B blocks, fp16, built directly by build_weights:
//   [tap t=slab*5+c][blk 0..3][16 rows x 48B (16 n*2B + pad)]
//   blk0=k00, blk1=base01, blk2=b10(raw), blk3=v11(diag)
__device__ __align__(16) unsigned char g_Bc[125 * 4 * 768];
// channel-last fp16 x: [b][x][y][z][ci'] (PERMUTED channels)
__device__ __align__(128) __half g_xh[2ull * 64 * 64 * 64 * 64];
// 16B zero source for halo cp.async
__device__ __align__(16) float g_zero[4] = {0.f, 0.f, 0.f, 0.f};

// channel permutation: orig 16+3u+i  ->  16+16i+u ; identity below 16
__device__ __forceinline__ int perm_ch(int ci) {
    if (ci < 16) return ci;
    const int r = ci - 16;
    return 16 + (r % 3) * 16 + (r / 3);
}

// ---------------------------------------------------------------------------
// Kernel 1: build compact B blocks (fp16) straight from inputs
// ---------------------------------------------------------------------------
__global__ void build_weights(const float* __restrict__ lw0,
                              const float* __restrict__ lw1,
                              const float* __restrict__ tp)
{
    const int t  = blockIdx.x;            // 0..124, t = (a*5+bb)*5 + c
    const int a  = t / 25;
    const int b2 = (t / 5) % 5;
    const int c  = t % 5;

    const float lx = -1.f + 0.5f * (float)a;
    const float ly = -1.f + 0.5f * (float)b2;
    const float lz = -1.f + 0.5f * (float)c;
    const float d  = sqrtf(lx*lx + ly*ly + lz*lz);

    const float scale = cosf(3.14159265358979323846f * d) / 11.180339887498949f;
    float coef[5];
#pragma unroll
    for (int s = 0; s < 5; s++) {
        float u = (d - 0.25f * (float)s) / 0.25f;
        coef[s] = expf(-u * u) * (1.0f / 1.12f) * scale;
    }

    const int u_ = threadIdx.x >> 4;
    const int w_ = threadIdx.x & 15;
    const int m  = u_ * 16 + w_;

    float eA = 0.f, eB = 0.f, eC = 0.f, eD = 0.f;
#pragma unroll
    for (int s = 0; s < 5; s++) {
        const float cs = coef[s];
        eA += cs * tp[s * 1024 +   0 + m];
        eB += cs * tp[s * 1024 + 256 + m];
        eC += cs * tp[s * 1024 + 512 + m];
        eD += cs * tp[s * 1024 + 768 + m];
    }

    const float A0  = 0.17677669529663689f;   // sqrt(1/32)
    const float A1  = 0.30618621784789724f;   // sqrt(3/32)
    const float IS3 = 0.57735026918962576f;   // 1/sqrt(3)
    const float inv = 0.25f;
    const bool  center = (t == 62);           // (2,2,2)

    float blkv[4];
    blkv[0] = 0.1f * A0 * eA + (center ? inv * lw0[m] : 0.f);     // k00
    blkv[1] = 0.1f * A1 * IS3 * eB;                                // base01
    blkv[2] = 0.1f * A0 * IS3 * eD;                                // b10 raw
    blkv[3] = 0.1f * A1 * IS3 * eC + (center ? inv * lw1[m] : 0.f);// v11

#pragma unroll
    for (int blk = 0; blk < 4; blk++) {
        const size_t off = (size_t)(t * 4 + blk) * 768
                         + (size_t)u_ * 48 + (size_t)w_ * 2;
        *(__half*)(g_Bc + off) = __float2half(blkv[blk]);
    }
}

// ---------------------------------------------------------------------------
// Kernel 2: transpose x -> channel-last (PERMUTED) fp16
// ---------------------------------------------------------------------------
__global__ void __launch_bounds__(256) xsplit(const float* __restrict__ x)
{
    __shared__ float s[64][65];
    const int gid = blockIdx.x;            // b*4096 + xx*64 + y
    const int y  = gid & 63;
    const int xx = (gid >> 6) & 63;
    const int b  = gid >> 12;
    const int tid = threadIdx.x;
    const int zz = tid & 63;
    const int cq = tid >> 6;               // 0..3

    const size_t sp = (size_t)(xx * 64 + y) * 64;
#pragma unroll
    for (int r = 0; r < 16; r++) {
        const int ci = cq * 16 + r;
        s[ci][zz] = x[(size_t)(b * 64 + ci) * 262144 + sp + zz];
    }
    __syncthreads();

    __half* oH = g_xh + (((size_t)(b * 64 + xx) * 64 + y) << 12);
    const int ci_w = tid & 63;
    const int cp   = perm_ch(ci_w);
#pragma unroll
    for (int r = 0; r < 16; r++) {
        const int z = cq * 16 + r;
        oH[z * 64 + cp] = __float2half(s[ci_w][z]);
    }
}

// ---------------------------------------------------------------------------
// PTX / fp16 helpers
// ---------------------------------------------------------------------------
__device__ __forceinline__ uint32_t smem_u32(const void* p) {
    uint32_t a;
    asm("{ .reg .u64 t; cvta.to.shared.u64 t, %1; cvt.u32.u64 %0, t; }"
        : "=r"(a) : "l"(p));
    return a;
}
__device__ __forceinline__ void ldsm4(uint32_t& r0, uint32_t& r1,
                                      uint32_t& r2, uint32_t& r3, uint32_t a) {
    asm volatile("ldmatrix.sync.aligned.m8n8.x4.shared.b16 {%0,%1,%2,%3}, [%4];"
                 : "=r"(r0), "=r"(r1), "=r"(r2), "=r"(r3) : "r"(a));
}
__device__ __forceinline__ void ldsm4t(uint32_t& r0, uint32_t& r1,
                                       uint32_t& r2, uint32_t& r3, uint32_t a) {
    asm volatile("ldmatrix.sync.aligned.m8n8.x4.trans.shared.b16 {%0,%1,%2,%3}, [%4];"
                 : "=r"(r0), "=r"(r1), "=r"(r2), "=r"(r3) : "r"(a));
}
__device__ __forceinline__ void mma16816(float* d, uint32_t a0, uint32_t a1,
                                         uint32_t a2, uint32_t a3,
                                         uint32_t b0, uint32_t b1) {
    asm volatile(
        "mma.sync.aligned.m16n8k16.row.col.f32.f16.f16.f32 "
        "{%0,%1,%2,%3}, {%4,%5,%6,%7}, {%8,%9}, {%0,%1,%2,%3};"
        : "+f"(d[0]), "+f"(d[1]), "+f"(d[2]), "+f"(d[3])
        : "r"(a0), "r"(a1), "r"(a2), "r"(a3), "r"(b0), "r"(b1));
}
__device__ __forceinline__ uint32_t hmul2u(uint32_t a, uint32_t s) {
    __half2 r = __hmul2(*(__half2*)&a, *(__half2*)&s);
    return *(uint32_t*)&r;
}
__device__ __forceinline__ uint32_t hfma2u(uint32_t a, uint32_t s, uint32_t c) {
    __half2 r = __hfma2(*(__half2*)&a, *(__half2*)&s, *(__half2*)&c);
    return *(uint32_t*)&r;
}
__device__ __forceinline__ void cpa16(uint32_t dst, const void* src) {
    asm volatile("cp.async.cg.shared.global [%0], [%1], 16;"
                 :: "r"(dst), "l"(src));
}
#define CP_COMMIT() asm volatile("cp.async.commit_group;" ::: "memory")
#define CP_WAIT0()  asm volatile("cp.async.wait_group 0;" ::: "memory")

// ---------------------------------------------------------------------------
// SMEM map (bytes, within dynamic smem)
//   B: 2 bufs x 15360 (5c x 4blk x 768B)           =  30720
//   Input: 2 stages x 4 ys x 64 rows x 128B        =  65536
// ---------------------------------------------------------------------------
#define SM_B     0
#define SM_IN    30720
#define SM_ZERO  96256
#define SM_TOT   96384
#define PLANE_B  15360

// ---------------------------------------------------------------------------
// Kernel 3: mma.sync implicit-GEMM conv, pure fp16, M=256 per CTA,
//           2 CTAs/SM, k10 rank-1 factored on A side (HFMA2 combine).
//   per c-tap per mt: blk0(2) + blk1->P(2) + blk3 diag(6) + Ac*b10(2) = 12 MMA
// ---------------------------------------------------------------------------
__global__ void __launch_bounds__(256, 2)
conv_mma(float* __restrict__ out)
{
    extern __shared__ char smem[];
    const uint32_t sb = smem_u32(smem);
    const int tid  = threadIdx.x;
    const int wid  = tid >> 5;
    const int lane = tid & 31;

    const int gid = blockIdx.x;                  // 2*64*16 = 2048 CTAs
    const int y0  = (gid & 15) * 4;
    const int x0  = (gid >> 4) & 63;
    const int b   = gid >> 10;

    if (tid < 8)
        *(float4*)(smem + SM_ZERO + tid * 16) = make_float4(0.f, 0.f, 0.f, 0.f);

    // plane list (uniform across block)
    int pslab[25], pxi[25], pbb[25];
    int npl = 0;
#pragma unroll
    for (int a = 0; a < 5; a++) {
        const int xi = x0 + a - 2;
        if ((unsigned)xi >= 64u) continue;
#pragma unroll
        for (int bb = 0; bb < 5; bb++) {
            const int ylo = y0 + bb - 2;
            const int yhi = ylo + 3;
            if (yhi < 0 || ylo > 63) continue;
            pslab[npl] = a * 5 + bb;
            pxi[npl]   = xi;
            pbb[npl]   = bb;
            npl++;
        }
    }

    // per-warp / per-thread constants
    const int zb   = (wid & 3) * 16;
    const int ysw  = wid >> 2;                   // ys pair base = ysw*2
    const int mloc = (lane & 7) + ((lane >> 3) & 1) * 8;
    const int ksub = lane >> 4;
    const uint32_t zeroAddr = sb + SM_ZERO;
    const uint32_t bl_off = (uint32_t)(lane & 15) * 48u + (uint32_t)(lane >> 4) * 16u;
    float acc[2][8][4];
#pragma unroll
    for (int mt = 0; mt < 2; mt++)
#pragma unroll
        for (int nt = 0; nt < 8; nt++)
#pragma unroll
            for (int i = 0; i < 4; i++) acc[mt][nt][i] = 0.f;

    // staging lambdas -------------------------------------------------------
    auto stage_B = [&](int p, int buf) {
        const unsigned char* src = g_Bc + (size_t)pslab[p] * PLANE_B;
        const uint32_t dst0 = sb + SM_B + buf * PLANE_B;
#pragma unroll
        for (int i = 0; i < 4; i++) {
            const int id = tid + i * 256;        // 0..1023, guard at 960
            if (id < PLANE_B / 16)
                cpa16(dst0 + id * 16, src + id * 16);
        }
    };
    auto stage_In = [&](int p, int stg) {
        const int xi = pxi[p], bb = pbb[p];
#pragma unroll
        for (int i = 0; i < 8; i++) {
            const int id   = tid + i * 256;      // 0..2047
            const int col  = id & 7;
            const int z    = (id >> 3) & 63;
            const int ys   = (id >> 9) & 3;
            const int yi   = y0 + ys + bb - 2;
            const bool ok  = (unsigned)yi < 64u;
            const void* src = ok
                ? (const void*)(g_xh + (((size_t)(b * 64 + xi) * 64 + yi) << 12)
                                + z * 64 + col * 8)
                : (const void*)g_zero;
            const uint32_t dst = sb + SM_IN + stg * 32768
                               + ys * 8192 + z * 128
                               + (((uint32_t)col * 16u) ^ (((uint32_t)z & 7u) << 4));
            cpa16(dst, src);
        }
    };

    // prologue
    stage_B(0, 0);
    stage_In(0, 0);
    CP_COMMIT();
    CP_WAIT0();
    __syncthreads();

#pragma unroll 1
    for (int p = 0; p < npl; p++) {
        if (p + 1 < npl) {
            stage_B(p + 1, (p + 1) & 1);
            stage_In(p + 1, (p + 1) & 1);
            CP_COMMIT();
        }

        const uint32_t Bb   = sb + SM_B + (p & 1) * PLANE_B;
        const uint32_t inSt = sb + SM_IN + (p & 1) * 32768;

        const int slab = pslab[p];
        const int pa   = slab / 5;
        const int pb   = slab - pa * 5;
        const float lx = -1.f + 0.5f * (float)pa;
        const float ly = -1.f + 0.5f * (float)pb;

        // ---- compute: 5 c-taps ----
#pragma unroll 1
        for (int c = 0; c < 5; c++) {
            const float lz = -1.f + 0.5f * (float)c;
            const float d2 = lx*lx + ly*ly + lz*lz;
            float s[3];
            if (d2 > 0.f) {
                const float ri = rsqrtf(d2) * 1.7320508075688772f;
                s[0] = ly * ri; s[1] = lz * ri; s[2] = lx * ri;
            } else { s[0] = s[1] = s[2] = 0.f; }
            uint32_t s2u[3];
#pragma unroll
            for (int k = 0; k < 3; k++) {
                __half2 h = __float2half2_rn(s[k]);
                s2u[k] = *(uint32_t*)&h;
            }

            const int zi = zb + mloc + c - 2;
            const bool vz = (unsigned)zi < 64u;
            const uint32_t jx   = ((uint32_t)zi & 7u) << 4;
            const uint32_t arow = (uint32_t)zi * 128u;
            const uint32_t cbase = Bb + (uint32_t)(c * 4) * 768u + bl_off;

            // persistent B fragments: b10 raw (blk2) and v11 diag (blk3)
            uint32_t b20, b21, b22, b23, b30, b31, b32, b33;
            ldsm4t(b20, b21, b22, b23, cbase + 2 * 768);
            ldsm4t(b30, b31, b32, b33, cbase + 3 * 768);

            uint32_t a[2][4], Ac[2][4];
            uint32_t t0, t1, t2, t3;

            // ---- q=0: blk0 (k00) + blk1 (k01 rank-1 out) ----
            {
                const uint32_t acol = ((uint32_t)(ksub * 16)) ^ jx;
#pragma unroll
                for (int mt = 0; mt < 2; mt++) {
                    const uint32_t inH = inSt + (ysw * 2 + mt) * 8192;
                    const uint32_t aA = vz ? (inH + arow + acol) : zeroAddr;
                    ldsm4(a[mt][0], a[mt][1], a[mt][2], a[mt][3], aA);
                }
                ldsm4t(t0, t1, t2, t3, cbase + 0 * 768);
#pragma unroll
                for (int mt = 0; mt < 2; mt++) {
                    mma16816(acc[mt][0], a[mt][0], a[mt][1], a[mt][2], a[mt][3], t0, t1);
                    mma16816(acc[mt][1], a[mt][0], a[mt][1], a[mt][2], a[mt][3], t2, t3);
                }
                ldsm4t(t0, t1, t2, t3, cbase + 1 * 768);
#pragma unroll
                for (int mt = 0; mt < 2; mt++) {
                    float P[2][4];
#pragma unroll
                    for (int j = 0; j < 2; j++)
#pragma unroll
                        for (int r = 0; r < 4; r++) P[j][r] = 0.f;
                    mma16816(P[0], a[mt][0], a[mt][1], a[mt][2], a[mt][3], t0, t1);
                    mma16816(P[1], a[mt][0], a[mt][1], a[mt][2], a[mt][3], t2, t3);
#pragma unroll
                    for (int k = 0; k < 3; k++) {
                        const float sk = s[k];
#pragma unroll
                        for (int j = 0; j < 2; j++)
#pragma unroll
                            for (int r = 0; r < 4; r++)
                                acc[mt][2 * (k + 1) + j][r] += sk * P[j][r];
                    }
                }
            }

            // ---- q=1..3: blk3 diag MMAs + fp16 combine Ac += s[k]*A_q ----
#pragma unroll
            for (int k = 0; k < 3; k++) {
                const int q = k + 1;
                const uint32_t acol = ((uint32_t)(q * 32 + ksub * 16)) ^ jx;
#pragma unroll
                for (int mt = 0; mt < 2; mt++) {
                    const uint32_t inH = inSt + (ysw * 2 + mt) * 8192;
                    const uint32_t aA = vz ? (inH + arow + acol) : zeroAddr;
                    ldsm4(a[mt][0], a[mt][1], a[mt][2], a[mt][3], aA);
                }
#pragma unroll
                for (int mt = 0; mt < 2; mt++) {
                    mma16816(acc[mt][2 * (k + 1)],     a[mt][0], a[mt][1], a[mt][2], a[mt][3], b30, b31);
                    mma16816(acc[mt][2 * (k + 1) + 1], a[mt][0], a[mt][1], a[mt][2], a[mt][3], b32, b33);
#pragma unroll
                    for (int r = 0; r < 4; r++) {
                        if (k == 0) Ac[mt][r] = hmul2u(a[mt][r], s2u[0]);
                        else        Ac[mt][r] = hfma2u(a[mt][r], s2u[k], Ac[mt][r]);
                    }
                }
            }

            // ---- blk2: combined-A x raw b10 -> acc n-block 0 ----
#pragma unroll
            for (int mt = 0; mt < 2; mt++) {
                mma16816(acc[mt][0], Ac[mt][0], Ac[mt][1], Ac[mt][2], Ac[mt][3], b20, b21);
                mma16816(acc[mt][1], Ac[mt][0], Ac[mt][1], Ac[mt][2], Ac[mt][3], b22, b23);
            }
        }

        if (p + 1 < npl) CP_WAIT0();
        __syncthreads();
    }

    // ---- epilogue: direct global stores, un-permute cout ----
    const int g  = lane >> 2;
    const int cc = lane & 3;
    const int z  = zb + g;
#pragma unroll
    for (int mt = 0; mt < 2; mt++) {
        const int y = y0 + ysw * 2 + mt;
        float* ob = out + ((((size_t)b * 64) * 64 + x0) * 64 + y) * 64 + z;
#pragma unroll
        for (int nt = 0; nt < 8; nt++) {
            const int n0 = nt * 8 + 2 * cc;
            const int ch0 = (n0 < 16) ? n0 : (16 + 3 * ((n0 - 16) & 15) + ((n0 - 16) >> 4));
            const int n1 = n0 + 1;
            const int ch1 = (n1 < 16) ? n1 : (16 + 3 * ((n1 - 16) & 15) + ((n1 - 16) >> 4));
            float* p0 = ob + (size_t)ch0 * 262144;
            float* p1 = ob + (size_t)ch1 * 262144;
            p0[0] = acc[mt][nt][0];
            p1[0] = acc[mt][nt][1];
            p0[8] = acc[mt][nt][2];
            p1[8] = acc[mt][nt][3];
        }
    }
}

// ---------------------------------------------------------------------------
// Launch
// ---------------------------------------------------------------------------
extern "C" void kernel_launch(void* const* d_in, const int* in_sizes, int n_in,
                              void* d_out, int out_size)
{
    const float* x   = (const float*)d_in[0];
    const float* lw0 = (const float*)d_in[1];
    const float* lw1 = (const float*)d_in[2];
    const float* tp  = (const float*)d_in[3];
    float* out = (float*)d_out;

    xsplit<<<2 * 64 * 64, 256>>>(x);
    build_weights<<<125, 256>>>(lw0, lw1, tp);

    cudaFuncSetAttribute(conv_mma, cudaFuncAttributeMaxDynamicSharedMemorySize,
                         SM_TOT);
    conv_mma<<<2 * 64 * 16, 256, SM_TOT>>>(out);
}